// round 10
// baseline (speedup 1.0000x reference)
#include <cuda_runtime.h>
#include <cuda_bf16.h>
#include <cuda_fp16.h>
#include <cstdint>

#define N_NODES 50000
#define N_EDGES 800000
#define NFEAT   512
#define NHID    64
#define NHEAD   8
#define F1      512      // NHEAD*NHID
#define NCLASS  40
#define N2PAD   64
#define NEG     0.2f

// ---------------- scratch ---------------------------------------------------
__device__ __half g_h1h[(size_t)N_NODES * F1];   // fp16 gather copy of h1
__device__ float g_h2[(size_t)N_NODES * NCLASS];
__device__ float g_s1s[N_NODES * NHEAD];
__device__ float g_s1d[N_NODES * NHEAD];
__device__ float g_s2s[N_NODES];
__device__ float g_s2d[N_NODES];
__device__ int   g_deg[N_NODES];
__device__ int   g_off[N_NODES + 1];
__device__ int   g_cur[N_NODES];
__device__ int   g_csr_src[N_EDGES];
__device__ int   g_bsum[64];
__device__ int   g_bpre[64];
// bf16 split operands
__device__ __nv_bfloat16 g_xhi[(size_t)N_NODES * NFEAT];
__device__ __nv_bfloat16 g_xlo[(size_t)N_NODES * NFEAT];
__device__ __nv_bfloat16 g_WThi[F1 * NFEAT];   // [n][k], n = h*64+c
__device__ __nv_bfloat16 g_WTlo[F1 * NFEAT];
__device__ __nv_bfloat16 g_zhi[(size_t)N_NODES * F1];   // layer-2 input, split
__device__ __nv_bfloat16 g_zlo[(size_t)N_NODES * F1];
__device__ __nv_bfloat16 g_W2hi[N2PAD * F1];   // [n][k], n padded to 64
__device__ __nv_bfloat16 g_W2lo[N2PAD * F1];

__device__ __forceinline__ uint32_t smem_u32(const void* p) {
    uint32_t a;
    asm("{ .reg .u64 t; cvta.to.shared.u64 t, %1; cvt.u32.u64 %0, t; }" : "=r"(a) : "l"(p));
    return a;
}

#define LDSM_X4(r0, r1, r2, r3, addr) \
    asm volatile("ldmatrix.sync.aligned.m8n8.x4.shared.b16 {%0,%1,%2,%3}, [%4];" \
                 : "=r"(r0), "=r"(r1), "=r"(r2), "=r"(r3) : "r"(addr))
#define MMA16816(acc, a, b0, b1) \
    asm volatile("mma.sync.aligned.m16n8k16.row.col.f32.bf16.bf16.f32 " \
                 "{%0,%1,%2,%3}, {%4,%5,%6,%7}, {%8,%9}, {%0,%1,%2,%3};" \
                 : "+f"((acc)[0]), "+f"((acc)[1]), "+f"((acc)[2]), "+f"((acc)[3]) \
                 : "r"((a)[0]), "r"((a)[1]), "r"((a)[2]), "r"((a)[3]), "r"(b0), "r"(b1))

// ---------------- CSR construction ------------------------------------------
__global__ void k_zero_deg() {
    int i = blockIdx.x * blockDim.x + threadIdx.x;
    if (i < N_NODES) g_deg[i] = 0;
}
__global__ void k_zero_scores() {
    int i = blockIdx.x * blockDim.x + threadIdx.x;
    if (i < N_NODES * NHEAD) {
        g_s1s[i] = 0.f;
        g_s1d[i] = 0.f;
    }
    if (i < N_NODES) {
        g_s2s[i] = 0.f;
        g_s2d[i] = 0.f;
    }
}
__global__ void k_count(const int* __restrict__ dst) {
    int e = blockIdx.x * blockDim.x + threadIdx.x;
    if (e < N_EDGES) atomicAdd(&g_deg[dst[e]], 1);
}
__global__ __launch_bounds__(256) void k_scan_blk() {
    __shared__ int wsum[8];
    const int blk = blockIdx.x, t = threadIdx.x;
    const int base = blk * 1024 + t * 4;
    int v[4], s = 0;
#pragma unroll
    for (int j = 0; j < 4; j++) {
        int i = base + j;
        v[j] = (i < N_NODES) ? g_deg[i] : 0;
        s += v[j];
    }
    const int lane = t & 31, w = t >> 5;
    int ps = s;
#pragma unroll
    for (int o = 1; o < 32; o <<= 1) {
        int y = __shfl_up_sync(0xffffffffu, ps, o);
        if (lane >= o) ps += y;
    }
    if (lane == 31) wsum[w] = ps;
    __syncthreads();
    if (w == 0) {
        int ws = (lane < 8) ? wsum[lane] : 0;
#pragma unroll
        for (int o = 1; o < 8; o <<= 1) {
            int y = __shfl_up_sync(0xffffffffu, ws, o);
            if (lane >= o) ws += y;
        }
        if (lane < 8) wsum[lane] = ws;
    }
    __syncthreads();
    int run = ps - s + (w > 0 ? wsum[w - 1] : 0);
#pragma unroll
    for (int j = 0; j < 4; j++) {
        int i = base + j;
        if (i < N_NODES) g_off[i] = run;
        run += v[j];
    }
    if (t == 255) g_bsum[blk] = wsum[7];
}
__global__ void k_scan_top() {
    const int lane = threadIdx.x;
    const int nblk = (N_NODES + 1023) / 1024;
    int a = (lane < nblk) ? g_bsum[lane] : 0;
    int b = (lane + 32 < nblk) ? g_bsum[lane + 32] : 0;
    int pa = a;
#pragma unroll
    for (int o = 1; o < 32; o <<= 1) {
        int y = __shfl_up_sync(0xffffffffu, pa, o);
        if (lane >= o) pa += y;
    }
    int tot0 = __shfl_sync(0xffffffffu, pa, 31);
    int pb = b;
#pragma unroll
    for (int o = 1; o < 32; o <<= 1) {
        int y = __shfl_up_sync(0xffffffffu, pb, o);
        if (lane >= o) pb += y;
    }
    if (lane < nblk) g_bpre[lane] = pa - a;
    if (lane + 32 < nblk) g_bpre[lane + 32] = tot0 + pb - b;
}
__global__ void k_scan_add() {
    int i = blockIdx.x * blockDim.x + threadIdx.x;
    if (i < N_NODES) {
        int o = g_off[i] + g_bpre[i >> 10];
        g_off[i] = o;
        g_cur[i] = o;
    }
    if (i == 0) g_off[N_NODES] = N_EDGES;
}
__global__ void k_fill(const int* __restrict__ src, const int* __restrict__ dst) {
    int e = blockIdx.x * blockDim.x + threadIdx.x;
    if (e < N_EDGES) {
        int d = dst[e];
        int p = atomicAdd(&g_cur[d], 1);
        g_csr_src[p] = src[e];
    }
}

// ---------------- bf16 splits ------------------------------------------------
__global__ void k_split_x(const float* __restrict__ x) {
    int i = blockIdx.x * blockDim.x + threadIdx.x;
    const int total = N_NODES * NFEAT / 8;
    if (i >= total) return;
    const float4* p = (const float4*)x + (size_t)i * 2;
    float4 v0 = p[0], v1 = p[1];
    float f[8] = {v0.x, v0.y, v0.z, v0.w, v1.x, v1.y, v1.z, v1.w};
    __nv_bfloat16 hi[8], lo[8];
#pragma unroll
    for (int j = 0; j < 8; j++) {
        hi[j] = __float2bfloat16(f[j]);
        lo[j] = __float2bfloat16(f[j] - __bfloat162float(hi[j]));
    }
    *(uint4*)(g_xhi + (size_t)i * 8) = *(uint4*)hi;
    *(uint4*)(g_xlo + (size_t)i * 8) = *(uint4*)lo;
}
__global__ void k_split_w(const float* __restrict__ W1) {
    int idx = blockIdx.x * blockDim.x + threadIdx.x;
    if (idx >= F1 * NFEAT) return;
    int n = idx >> 9, k = idx & 511;
    int h = n >> 6, c = n & 63;
    float w = W1[((size_t)h * NFEAT + k) * NHID + c];
    __nv_bfloat16 hi = __float2bfloat16(w);
    __nv_bfloat16 lo = __float2bfloat16(w - __bfloat162float(hi));
    g_WThi[(size_t)n * NFEAT + k] = hi;
    g_WTlo[(size_t)n * NFEAT + k] = lo;
}
__global__ void k_split_w2(const float* __restrict__ W2) {
    int idx = blockIdx.x * blockDim.x + threadIdx.x;
    if (idx >= N2PAD * F1) return;
    int n = idx >> 9, k = idx & 511;
    float w = (n < NCLASS) ? W2[(size_t)k * NCLASS + n] : 0.f;
    __nv_bfloat16 hi = __float2bfloat16(w);
    __nv_bfloat16 lo = __float2bfloat16(w - __bfloat162float(hi));
    g_W2hi[(size_t)n * F1 + k] = hi;
    g_W2lo[(size_t)n * F1 + k] = lo;
}

// ---------------- GEMM1 (fused-split HMMA + fused scores) -------------------
#define G1_BM     128
#define G1_BN     128
#define G1_KITER  16                 // 512 / 32
#define G1_ROWB   80
#define G1_REG    10240
#define G1_STAGE  (4 * G1_REG)       // 40960
#define G1_SMEM   (2 * G1_STAGE)     // 81920

__device__ __forceinline__ void g1_prefetch(int kb, uint32_t stage, int bm, int bn, int t) {
    const int k_in = kb * 32;
#pragma unroll
    for (int i = 0; i < 8; i++) {
        int q = t + i * 256;
        int region = q >> 9;          // 0:Ahi 1:Alo 2:Bhi 3:Blo
        int idx = q & 511;
        int row = idx >> 2, c = idx & 3;
        uint32_t dst = stage + region * G1_REG + row * G1_ROWB + c * 16;
        if (region < 2) {
            int grow = bm + row;
            int ok = grow < N_NODES;
            if (!ok) grow = 0;
            const __nv_bfloat16* Asrc = region ? g_xlo : g_xhi;
            const void* srcp = Asrc + (size_t)grow * NFEAT + k_in + c * 8;
            int sz = ok ? 16 : 0;
            asm volatile("cp.async.cg.shared.global [%0], [%1], 16, %2;"
                         :: "r"(dst), "l"(srcp), "r"(sz));
        } else {
            const __nv_bfloat16* Bsrc = (region == 3) ? g_WTlo : g_WThi;
            const void* srcp = Bsrc + (size_t)(bn + row) * NFEAT + k_in + c * 8;
            asm volatile("cp.async.cg.shared.global [%0], [%1], 16;"
                         :: "r"(dst), "l"(srcp));
        }
    }
}

__global__ __launch_bounds__(256, 2) void k_gemm1_mma(const float* __restrict__ a1) {
    extern __shared__ char dyn[];
    const uint32_t sbase = smem_u32(dyn);
    const int t    = threadIdx.x;
    const int wid  = t >> 5;
    const int lane = t & 31;
    const int bm   = blockIdx.x * G1_BM;
    const int bn   = blockIdx.y * G1_BN;
    const int mw   = (wid >> 2) * 64;
    const int nw   = (wid & 3) * 32;

    float acc[4][4][4];
#pragma unroll
    for (int mt = 0; mt < 4; mt++)
#pragma unroll
        for (int nt = 0; nt < 4; nt++)
#pragma unroll
            for (int j = 0; j < 4; j++) acc[mt][nt][j] = 0.f;

    g1_prefetch(0, sbase, bm, bn, t);
    asm volatile("cp.async.commit_group;");
    g1_prefetch(1, sbase + G1_STAGE, bm, bn, t);
    asm volatile("cp.async.commit_group;");

    const uint32_t a_off = (mw + (lane & 15)) * G1_ROWB + ((lane >> 4) * 16);
    const uint32_t b_off = (nw + (lane & 7) + ((lane >> 4) << 3)) * G1_ROWB + (((lane >> 3) & 1) * 16);

    for (int kb = 0; kb < G1_KITER; kb++) {
        asm volatile("cp.async.wait_group 1;");
        __syncthreads();
        const uint32_t stage = sbase + (kb & 1) * G1_STAGE;

#pragma unroll
        for (int ks = 0; ks < 2; ks++) {
            uint32_t ahi[4][4], alo[4][4];
#pragma unroll
            for (int mt = 0; mt < 4; mt++) {
                uint32_t ad = stage + a_off + mt * (16 * G1_ROWB) + ks * 32;
                LDSM_X4(ahi[mt][0], ahi[mt][1], ahi[mt][2], ahi[mt][3], ad);
                LDSM_X4(alo[mt][0], alo[mt][1], alo[mt][2], alo[mt][3], ad + G1_REG);
            }
            uint32_t b[2][4];
#pragma unroll
            for (int np = 0; np < 2; np++) {
                uint32_t bd = stage + 2 * G1_REG + b_off + np * (16 * G1_ROWB) + ks * 32;
                LDSM_X4(b[np][0], b[np][1], b[np][2], b[np][3], bd);
            }
#pragma unroll
            for (int mt = 0; mt < 4; mt++)
#pragma unroll
                for (int nt = 0; nt < 4; nt++) {
                    const uint32_t b0 = b[nt >> 1][(nt & 1) * 2];
                    const uint32_t b1 = b[nt >> 1][(nt & 1) * 2 + 1];
                    MMA16816(acc[mt][nt], ahi[mt], b0, b1);
                    MMA16816(acc[mt][nt], alo[mt], b0, b1);
                }
#pragma unroll
            for (int np = 0; np < 2; np++) {
                uint32_t bd = stage + 3 * G1_REG + b_off + np * (16 * G1_ROWB) + ks * 32;
                LDSM_X4(b[np][0], b[np][1], b[np][2], b[np][3], bd);
            }
#pragma unroll
            for (int mt = 0; mt < 4; mt++)
#pragma unroll
                for (int nt = 0; nt < 4; nt++) {
                    const uint32_t b0 = b[nt >> 1][(nt & 1) * 2];
                    const uint32_t b1 = b[nt >> 1][(nt & 1) * 2 + 1];
                    MMA16816(acc[mt][nt], ahi[mt], b0, b1);
                }
        }
        __syncthreads();
        if (kb + 2 < G1_KITER)
            g1_prefetch(kb + 2, stage, bm, bn, t);
        asm volatile("cp.async.commit_group;");
    }

    // epilogue: fp16 h1h + fused layer-1 attention scores
    const int r_base = bm + mw + (lane >> 2);
    const int hw = (bn + nw) >> 6;
    const int co0 = ((bn + nw) & 63) + (lane & 3) * 2;
#pragma unroll
    for (int mt = 0; mt < 4; mt++) {
#pragma unroll
        for (int nt = 0; nt < 4; nt++) {
            int r0 = r_base + mt * 16;
            int cc = bn + nw + (lane & 3) * 2 + nt * 8;
            if (r0 < N_NODES)
                *(__half2*)(g_h1h + (size_t)r0 * F1 + cc) = __floats2half2_rn(acc[mt][nt][0], acc[mt][nt][1]);
            if (r0 + 8 < N_NODES)
                *(__half2*)(g_h1h + (size_t)(r0 + 8) * F1 + cc) = __floats2half2_rn(acc[mt][nt][2], acc[mt][nt][3]);
        }
        float s0 = 0.f, d0 = 0.f, s1 = 0.f, d1 = 0.f;
#pragma unroll
        for (int nt = 0; nt < 4; nt++) {
#pragma unroll
            for (int je = 0; je < 2; je++) {
                int co = co0 + nt * 8 + je;
                float a_s = a1[hw * 128 + co];
                float a_d = a1[hw * 128 + 64 + co];
                s0 += acc[mt][nt][je] * a_s;
                d0 += acc[mt][nt][je] * a_d;
                s1 += acc[mt][nt][2 + je] * a_s;
                d1 += acc[mt][nt][2 + je] * a_d;
            }
        }
        s0 += __shfl_xor_sync(0xffffffffu, s0, 1); s0 += __shfl_xor_sync(0xffffffffu, s0, 2);
        d0 += __shfl_xor_sync(0xffffffffu, d0, 1); d0 += __shfl_xor_sync(0xffffffffu, d0, 2);
        s1 += __shfl_xor_sync(0xffffffffu, s1, 1); s1 += __shfl_xor_sync(0xffffffffu, s1, 2);
        d1 += __shfl_xor_sync(0xffffffffu, d1, 1); d1 += __shfl_xor_sync(0xffffffffu, d1, 2);
        if ((lane & 3) == 0) {
            int r0 = r_base + mt * 16;
            if (r0 < N_NODES) {
                atomicAdd(&g_s1s[r0 * NHEAD + hw], s0);
                atomicAdd(&g_s1d[r0 * NHEAD + hw], d0);
            }
            if (r0 + 8 < N_NODES) {
                atomicAdd(&g_s1s[(r0 + 8) * NHEAD + hw], s1);
                atomicAdd(&g_s1d[(r0 + 8) * NHEAD + hw], d1);
            }
        }
    }
}

// ---------------- GEMM2 (fused-split HMMA + fused layer-2 scores) -----------
#define G2_BM     128
#define G2_KITER  16
#define G2_AREG   10240
#define G2_BREG   5120
#define G2_STAGE  (2 * G2_AREG + 2 * G2_BREG)   // 30720
#define G2_SMEM   (2 * G2_STAGE)                // 61440

__device__ __forceinline__ void g2_prefetch(int kb, uint32_t stage, int bm, int t) {
    const int k_in = kb * 32;
#pragma unroll
    for (int i = 0; i < 6; i++) {
        int q = t + i * 256;
        if (q < 1024) {
            int region = q >> 9;
            int idx = q & 511;
            int row = idx >> 2, c = idx & 3;
            uint32_t dst = stage + region * G2_AREG + row * G1_ROWB + c * 16;
            int grow = bm + row;
            int ok = grow < N_NODES;
            if (!ok) grow = 0;
            const __nv_bfloat16* Asrc = region ? g_zlo : g_zhi;
            const void* srcp = Asrc + (size_t)grow * F1 + k_in + c * 8;
            int sz = ok ? 16 : 0;
            asm volatile("cp.async.cg.shared.global [%0], [%1], 16, %2;"
                         :: "r"(dst), "l"(srcp), "r"(sz));
        } else {
            int qb = q - 1024;
            int region = qb >> 8;
            int idx = qb & 255;
            int row = idx >> 2, c = idx & 3;
            uint32_t dst = stage + 2 * G2_AREG + region * G2_BREG + row * G1_ROWB + c * 16;
            const __nv_bfloat16* Bsrc = region ? g_W2lo : g_W2hi;
            const void* srcp = Bsrc + (size_t)row * F1 + k_in + c * 8;
            asm volatile("cp.async.cg.shared.global [%0], [%1], 16;"
                         :: "r"(dst), "l"(srcp));
        }
    }
}

__global__ __launch_bounds__(256, 2) void k_gemm2_mma(const float* __restrict__ a2) {
    extern __shared__ char dyn[];
    const uint32_t sbase = smem_u32(dyn);
    const int t    = threadIdx.x;
    const int wid  = t >> 5;
    const int lane = t & 31;
    const int bm   = blockIdx.x * G2_BM;
    const int mw   = (wid >> 1) * 32;
    const int nw   = (wid & 1) * 32;

    float acc[2][4][4];
#pragma unroll
    for (int mt = 0; mt < 2; mt++)
#pragma unroll
        for (int nt = 0; nt < 4; nt++)
#pragma unroll
            for (int j = 0; j < 4; j++) acc[mt][nt][j] = 0.f;

    g2_prefetch(0, sbase, bm, t);
    asm volatile("cp.async.commit_group;");
    g2_prefetch(1, sbase + G2_STAGE, bm, t);
    asm volatile("cp.async.commit_group;");

    const uint32_t a_off = (mw + (lane & 15)) * G1_ROWB + ((lane >> 4) * 16);
    const uint32_t b_off = (nw + (lane & 7) + ((lane >> 4) << 3)) * G1_ROWB + (((lane >> 3) & 1) * 16);

    for (int kb = 0; kb < G2_KITER; kb++) {
        asm volatile("cp.async.wait_group 1;");
        __syncthreads();
        const uint32_t stage = sbase + (kb & 1) * G2_STAGE;

#pragma unroll
        for (int ks = 0; ks < 2; ks++) {
            uint32_t ahi[2][4], alo[2][4];
#pragma unroll
            for (int mt = 0; mt < 2; mt++) {
                uint32_t ad = stage + a_off + mt * (16 * G1_ROWB) + ks * 32;
                LDSM_X4(ahi[mt][0], ahi[mt][1], ahi[mt][2], ahi[mt][3], ad);
                LDSM_X4(alo[mt][0], alo[mt][1], alo[mt][2], alo[mt][3], ad + G2_AREG);
            }
            uint32_t b[2][4];
#pragma unroll
            for (int np = 0; np < 2; np++) {
                uint32_t bd = stage + 2 * G2_AREG + b_off + np * (16 * G1_ROWB) + ks * 32;
                LDSM_X4(b[np][0], b[np][1], b[np][2], b[np][3], bd);
            }
#pragma unroll
            for (int mt = 0; mt < 2; mt++)
#pragma unroll
                for (int nt = 0; nt < 4; nt++) {
                    const uint32_t b0 = b[nt >> 1][(nt & 1) * 2];
                    const uint32_t b1 = b[nt >> 1][(nt & 1) * 2 + 1];
                    MMA16816(acc[mt][nt], ahi[mt], b0, b1);
                    MMA16816(acc[mt][nt], alo[mt], b0, b1);
                }
#pragma unroll
            for (int np = 0; np < 2; np++) {
                uint32_t bd = stage + 2 * G2_AREG + G2_BREG + b_off + np * (16 * G1_ROWB) + ks * 32;
                LDSM_X4(b[np][0], b[np][1], b[np][2], b[np][3], bd);
            }
#pragma unroll
            for (int mt = 0; mt < 2; mt++)
#pragma unroll
                for (int nt = 0; nt < 4; nt++) {
                    const uint32_t b0 = b[nt >> 1][(nt & 1) * 2];
                    const uint32_t b1 = b[nt >> 1][(nt & 1) * 2 + 1];
                    MMA16816(acc[mt][nt], ahi[mt], b0, b1);
                }
        }
        __syncthreads();
        if (kb + 2 < G2_KITER)
            g2_prefetch(kb + 2, stage, bm, t);
        asm volatile("cp.async.commit_group;");
    }

    // epilogue: h2 store + fused layer-2 scores
    const int r_base = bm + mw + (lane >> 2);
    const int c_base = nw + (lane & 3) * 2;
    float s0 = 0.f, d0 = 0.f, s1 = 0.f, d1 = 0.f;
#pragma unroll
    for (int mt = 0; mt < 2; mt++) {
#pragma unroll
        for (int nt = 0; nt < 4; nt++) {
            int r0 = r_base + mt * 16;
            int cc = c_base + nt * 8;
            if (cc < NCLASS) {
                if (r0 < N_NODES)
                    *(float2*)(g_h2 + (size_t)r0 * NCLASS + cc) = make_float2(acc[mt][nt][0], acc[mt][nt][1]);
                if (r0 + 8 < N_NODES)
                    *(float2*)(g_h2 + (size_t)(r0 + 8) * NCLASS + cc) = make_float2(acc[mt][nt][2], acc[mt][nt][3]);
            }
        }
    }
#pragma unroll
    for (int mt = 0; mt < 2; mt++) {
        s0 = 0.f; d0 = 0.f; s1 = 0.f; d1 = 0.f;
#pragma unroll
        for (int nt = 0; nt < 4; nt++) {
#pragma unroll
            for (int je = 0; je < 2; je++) {
                int cc = c_base + nt * 8 + je;
                float a_s = (cc < NCLASS) ? a2[cc] : 0.f;
                float a_d = (cc < NCLASS) ? a2[NCLASS + cc] : 0.f;
                s0 += acc[mt][nt][je] * a_s;
                d0 += acc[mt][nt][je] * a_d;
                s1 += acc[mt][nt][2 + je] * a_s;
                d1 += acc[mt][nt][2 + je] * a_d;
            }
        }
        s0 += __shfl_xor_sync(0xffffffffu, s0, 1); s0 += __shfl_xor_sync(0xffffffffu, s0, 2);
        d0 += __shfl_xor_sync(0xffffffffu, d0, 1); d0 += __shfl_xor_sync(0xffffffffu, d0, 2);
        s1 += __shfl_xor_sync(0xffffffffu, s1, 1); s1 += __shfl_xor_sync(0xffffffffu, s1, 2);
        d1 += __shfl_xor_sync(0xffffffffu, d1, 1); d1 += __shfl_xor_sync(0xffffffffu, d1, 2);
        if ((lane & 3) == 0) {
            int r0 = r_base + mt * 16;
            if (r0 < N_NODES) {
                atomicAdd(&g_s2s[r0], s0);
                atomicAdd(&g_s2d[r0], d0);
            }
            if (r0 + 8 < N_NODES) {
                atomicAdd(&g_s2s[r0 + 8], s1);
                atomicAdd(&g_s2d[r0 + 8], d1);
            }
        }
    }
}

__device__ __forceinline__ float lrelu(float x) { return x > 0.f ? x : NEG * x; }

// ---------------- layer-1 softmax-aggregate (chunked alpha staging) ---------
__global__ __launch_bounds__(256) void k_agg1(const float* __restrict__ b1) {
    __shared__ float s_alpha[8][256];   // [warp][head*32 + edge-slot]
    __shared__ int   s_src[8][32];
    int n    = (blockIdx.x * blockDim.x + threadIdx.x) >> 5;
    int w    = (threadIdx.x >> 5);
    int lane = threadIdx.x & 31;
    if (n >= N_NODES) return;
    const int beg = g_off[n], end = g_off[n + 1];

    const int h  = lane & 7;
    const int es = lane >> 3;
    const float sdh = g_s1d[n * NHEAD + h];

    float m = -1e30f;
    for (int i = beg + es; i < end; i += 4) {
        int s = g_csr_src[i];
        float e = lrelu(g_s1s[s * NHEAD + h] + sdh);
        m = fmaxf(m, e);
    }
    m = fmaxf(m, __shfl_xor_sync(0xffffffffu, m, 8));
    m = fmaxf(m, __shfl_xor_sync(0xffffffffu, m, 16));

    float den = 0.f;
    for (int i = beg + es; i < end; i += 4) {
        int s = g_csr_src[i];
        float e = lrelu(g_s1s[s * NHEAD + h] + sdh);
        den += __expf(e - m);
    }
    den += __shfl_xor_sync(0xffffffffu, den, 8);
    den += __shfl_xor_sync(0xffffffffu, den, 16);
    den = fmaxf(den, 1e-16f);

    // broadcast per-head m/den/sdh to all lanes (head j lives in lane j)
    float m_all[8], rden_all[8], sdh_all[8];
#pragma unroll
    for (int j = 0; j < 8; j++) {
        m_all[j]    = __shfl_sync(0xffffffffu, m, j);
        rden_all[j] = 1.f / __shfl_sync(0xffffffffu, den, j);
        sdh_all[j]  = __shfl_sync(0xffffffffu, sdh, j);
    }

    float acc[16];
#pragma unroll
    for (int j = 0; j < 16; j++) acc[j] = 0.f;
    const int hl = lane >> 2;

    for (int cb = beg; cb < end; cb += 32) {
        const int cnt = min(32, end - cb);
        // phase A: edge-parallel alpha computation
        if (lane < cnt) {
            int s = g_csr_src[cb + lane];
            s_src[w][lane] = s;
#pragma unroll
            for (int j = 0; j < 8; j++) {
                float e = lrelu(g_s1s[s * NHEAD + j] + sdh_all[j]);
                s_alpha[w][j * 32 + lane] = __expf(e - m_all[j]) * rden_all[j];
            }
        }
        __syncwarp();
        // phase B: pure gather-FMA
        for (int e = 0; e < cnt; e++) {
            int s = s_src[w][e];
            float alpha = s_alpha[w][hl * 32 + e];
            const uint4* hp = (const uint4*)(g_h1h + (size_t)s * F1 + lane * 16);
            uint4 q0 = hp[0];
            uint4 q1 = hp[1];
            float2 f;
            f = __half22float2(*(__half2*)&q0.x); acc[0] += alpha * f.x; acc[1] += alpha * f.y;
            f = __half22float2(*(__half2*)&q0.y); acc[2] += alpha * f.x; acc[3] += alpha * f.y;
            f = __half22float2(*(__half2*)&q0.z); acc[4] += alpha * f.x; acc[5] += alpha * f.y;
            f = __half22float2(*(__half2*)&q0.w); acc[6] += alpha * f.x; acc[7] += alpha * f.y;
            f = __half22float2(*(__half2*)&q1.x); acc[8] += alpha * f.x; acc[9] += alpha * f.y;
            f = __half22float2(*(__half2*)&q1.y); acc[10] += alpha * f.x; acc[11] += alpha * f.y;
            f = __half22float2(*(__half2*)&q1.z); acc[12] += alpha * f.x; acc[13] += alpha * f.y;
            f = __half22float2(*(__half2*)&q1.w); acc[14] += alpha * f.x; acc[15] += alpha * f.y;
        }
        __syncwarp();
    }

    const float4* bp = (const float4*)(b1 + lane * 16);
#pragma unroll
    for (int j = 0; j < 4; j++) {
        float4 b = bp[j];
        float v[4];
        v[0] = acc[j * 4 + 0] + b.x;
        v[1] = acc[j * 4 + 1] + b.y;
        v[2] = acc[j * 4 + 2] + b.z;
        v[3] = acc[j * 4 + 3] + b.w;
        __nv_bfloat16 hi[4], lo[4];
#pragma unroll
        for (int q = 0; q < 4; q++) {
            float e = v[q] > 0.f ? v[q] : expm1f(v[q]);
            hi[q] = __float2bfloat16(e);
            lo[q] = __float2bfloat16(e - __bfloat162float(hi[q]));
        }
        *(uint2*)(g_zhi + (size_t)n * F1 + lane * 16 + j * 4) = *(uint2*)hi;
        *(uint2*)(g_zlo + (size_t)n * F1 + lane * 16 + j * 4) = *(uint2*)lo;
    }
}

// ---------------- layer-2 aggregate + bias + log_softmax --------------------
__global__ __launch_bounds__(256) void k_agg2(const float* __restrict__ b2,
                                              float* __restrict__ out) {
    int n    = (blockIdx.x * blockDim.x + threadIdx.x) >> 5;
    int lane = threadIdx.x & 31;
    if (n >= N_NODES) return;
    const int beg = g_off[n], end = g_off[n + 1];
    const float sdn = g_s2d[n];

    float m = -1e30f;
    for (int i = beg + lane; i < end; i += 32) {
        int s = g_csr_src[i];
        m = fmaxf(m, lrelu(g_s2s[s] + sdn));
    }
#pragma unroll
    for (int off = 16; off > 0; off >>= 1)
        m = fmaxf(m, __shfl_xor_sync(0xffffffffu, m, off));

    float den = 0.f;
    for (int i = beg + lane; i < end; i += 32) {
        int s = g_csr_src[i];
        den += __expf(lrelu(g_s2s[s] + sdn) - m);
    }
#pragma unroll
    for (int off = 16; off > 0; off >>= 1)
        den += __shfl_xor_sync(0xffffffffu, den, off);
    den = fmaxf(den, 1e-16f);

    float acc0 = 0.f, acc1 = 0.f;
    for (int i = beg; i < end; i++) {
        int s = g_csr_src[i];
        float e = lrelu(g_s2s[s] + sdn);
        float alpha = __expf(e - m) / den;
        acc0 += alpha * g_h2[(size_t)s * NCLASS + lane];
        if (lane < 8) acc1 += alpha * g_h2[(size_t)s * NCLASS + 32 + lane];
    }

    float v0 = acc0 + b2[lane];
    float v1 = (lane < 8) ? (acc1 + b2[32 + lane]) : -1e30f;

    float mx = fmaxf(v0, v1);
#pragma unroll
    for (int off = 16; off > 0; off >>= 1)
        mx = fmaxf(mx, __shfl_xor_sync(0xffffffffu, mx, off));
    float se = __expf(v0 - mx) + ((lane < 8) ? __expf(v1 - mx) : 0.f);
#pragma unroll
    for (int off = 16; off > 0; off >>= 1)
        se += __shfl_xor_sync(0xffffffffu, se, off);
    float ls = logf(se);

    out[(size_t)n * NCLASS + lane] = v0 - mx - ls;
    if (lane < 8) out[(size_t)n * NCLASS + 32 + lane] = v1 - mx - ls;
}

// ---------------- launch -----------------------------------------------------
extern "C" void kernel_launch(void* const* d_in, const int* in_sizes, int n_in,
                              void* d_out, int out_size) {
    const float* x  = (const float*)d_in[0];
    const int*   el = (const int*)d_in[1];
    const float* W1 = (const float*)d_in[2];
    const float* a1 = (const float*)d_in[3];
    const float* b1 = (const float*)d_in[4];
    const float* W2 = (const float*)d_in[5];
    const float* a2 = (const float*)d_in[6];
    const float* b2 = (const float*)d_in[7];
    float* out = (float*)d_out;

    const int* src = el;
    const int* dst = el + N_EDGES;

    static cudaStream_t s2 = nullptr;
    static cudaEvent_t ev_fork = nullptr, ev_join = nullptr;
    if (!s2) {
        cudaStreamCreateWithFlags(&s2, cudaStreamNonBlocking);
        cudaEventCreateWithFlags(&ev_fork, cudaEventDisableTiming);
        cudaEventCreateWithFlags(&ev_join, cudaEventDisableTiming);
        cudaFuncSetAttribute(k_gemm1_mma, cudaFuncAttributeMaxDynamicSharedMemorySize, G1_SMEM);
        cudaFuncSetAttribute(k_gemm2_mma, cudaFuncAttributeMaxDynamicSharedMemorySize, G2_SMEM);
    }

    const int TB = 256;
    const int NBLK = (N_NODES + 1023) / 1024;

    // main stream: split + zero + gemm1 (gemm1 = submission index 3 for ncu)
    k_split_x<<<(N_NODES * NFEAT / 8 + TB - 1) / TB, TB>>>(x);                    // 0
    k_split_w<<<(F1 * NFEAT + TB - 1) / TB, TB>>>(W1);                            // 1
    k_zero_scores<<<(N_NODES * NHEAD + TB - 1) / TB, TB>>>();                     // 2
    k_gemm1_mma<<<dim3((N_NODES + G1_BM - 1) / G1_BM, F1 / G1_BN), 256, G1_SMEM>>>(a1); // 3
    cudaEventRecord(ev_fork, 0);

    // side stream: CSR build + W2 split (independent of gemm1)
    cudaStreamWaitEvent(s2, ev_fork, 0);
    k_zero_deg<<<(N_NODES + TB - 1) / TB, TB, 0, s2>>>();
    k_count<<<(N_EDGES + TB - 1) / TB, TB, 0, s2>>>(dst);
    k_scan_blk<<<NBLK, 256, 0, s2>>>();
    k_scan_top<<<1, 32, 0, s2>>>();
    k_scan_add<<<(N_NODES + TB - 1) / TB, TB, 0, s2>>>();
    k_fill<<<(N_EDGES + TB - 1) / TB, TB, 0, s2>>>(src, dst);
    k_split_w2<<<(N2PAD * F1 + TB - 1) / TB, TB, 0, s2>>>(W2);
    cudaEventRecord(ev_join, s2);

    // main stream rejoins, then the dependent chain
    cudaStreamWaitEvent(0, ev_join, 0);
    k_agg1<<<(N_NODES + 7) / 8, 256>>>(b1);
    k_gemm2_mma<<<(N_NODES + G2_BM - 1) / G2_BM, 256, G2_SMEM>>>(a2);
    k_agg2<<<(N_NODES + 7) / 8, 256>>>(b2, out);
}

// round 13
// speedup vs baseline: 1.0787x; 1.0787x over previous
#include <cuda_runtime.h>
#include <cuda_bf16.h>
#include <cuda_fp16.h>
#include <cstdint>

#define N_NODES 50000
#define N_EDGES 800000
#define NFEAT   512
#define NHID    64
#define NHEAD   8
#define F1      512      // NHEAD*NHID
#define NCLASS  40
#define N2PAD   64
#define NEG     0.2f

// ---------------- scratch ---------------------------------------------------
__device__ __half g_h1h[(size_t)N_NODES * F1];   // fp16 gather copy of h1
__device__ float g_h2[(size_t)N_NODES * NCLASS];
__device__ float g_s1s[N_NODES * NHEAD];
__device__ float g_s1d[N_NODES * NHEAD];
__device__ float g_s2s[N_NODES];
__device__ float g_s2d[N_NODES];
__device__ int   g_deg[N_NODES];
__device__ int   g_off[N_NODES + 1];
__device__ int   g_cur[N_NODES];
__device__ int   g_csr_src[N_EDGES];
__device__ int   g_bsum[64];
__device__ int   g_bpre[64];
// bf16 split operands
__device__ __nv_bfloat16 g_xhi[(size_t)N_NODES * NFEAT];
__device__ __nv_bfloat16 g_xlo[(size_t)N_NODES * NFEAT];
__device__ __nv_bfloat16 g_WThi[F1 * NFEAT];   // [n][k], n = h*64+c
__device__ __nv_bfloat16 g_WTlo[F1 * NFEAT];
__device__ __nv_bfloat16 g_zhi[(size_t)N_NODES * F1];   // layer-2 input, split
__device__ __nv_bfloat16 g_zlo[(size_t)N_NODES * F1];
__device__ __nv_bfloat16 g_W2hi[N2PAD * F1];   // [n][k], n padded to 64
__device__ __nv_bfloat16 g_W2lo[N2PAD * F1];

__device__ __forceinline__ uint32_t smem_u32(const void* p) {
    uint32_t a;
    asm("{ .reg .u64 t; cvta.to.shared.u64 t, %1; cvt.u32.u64 %0, t; }" : "=r"(a) : "l"(p));
    return a;
}

#define LDSM_X4(r0, r1, r2, r3, addr) \
    asm volatile("ldmatrix.sync.aligned.m8n8.x4.shared.b16 {%0,%1,%2,%3}, [%4];" \
                 : "=r"(r0), "=r"(r1), "=r"(r2), "=r"(r3) : "r"(addr))
#define MMA16816(acc, a, b0, b1) \
    asm volatile("mma.sync.aligned.m16n8k16.row.col.f32.bf16.bf16.f32 " \
                 "{%0,%1,%2,%3}, {%4,%5,%6,%7}, {%8,%9}, {%0,%1,%2,%3};" \
                 : "+f"((acc)[0]), "+f"((acc)[1]), "+f"((acc)[2]), "+f"((acc)[3]) \
                 : "r"((a)[0]), "r"((a)[1]), "r"((a)[2]), "r"((a)[3]), "r"(b0), "r"(b1))

// ---------------- CSR construction ------------------------------------------
__global__ void k_zero_deg() {
    int i = blockIdx.x * blockDim.x + threadIdx.x;
    if (i < N_NODES) g_deg[i] = 0;
}
__global__ void k_zero_scores() {
    int i = blockIdx.x * blockDim.x + threadIdx.x;
    if (i < N_NODES * NHEAD) {
        g_s1s[i] = 0.f;
        g_s1d[i] = 0.f;
    }
    if (i < N_NODES) {
        g_s2s[i] = 0.f;
        g_s2d[i] = 0.f;
    }
}
__global__ void k_count(const int* __restrict__ dst) {
    int e = blockIdx.x * blockDim.x + threadIdx.x;
    if (e < N_EDGES) atomicAdd(&g_deg[dst[e]], 1);
}
__global__ __launch_bounds__(256) void k_scan_blk() {
    __shared__ int wsum[8];
    const int blk = blockIdx.x, t = threadIdx.x;
    const int base = blk * 1024 + t * 4;
    int v[4], s = 0;
#pragma unroll
    for (int j = 0; j < 4; j++) {
        int i = base + j;
        v[j] = (i < N_NODES) ? g_deg[i] : 0;
        s += v[j];
    }
    const int lane = t & 31, w = t >> 5;
    int ps = s;
#pragma unroll
    for (int o = 1; o < 32; o <<= 1) {
        int y = __shfl_up_sync(0xffffffffu, ps, o);
        if (lane >= o) ps += y;
    }
    if (lane == 31) wsum[w] = ps;
    __syncthreads();
    if (w == 0) {
        int ws = (lane < 8) ? wsum[lane] : 0;
#pragma unroll
        for (int o = 1; o < 8; o <<= 1) {
            int y = __shfl_up_sync(0xffffffffu, ws, o);
            if (lane >= o) ws += y;
        }
        if (lane < 8) wsum[lane] = ws;
    }
    __syncthreads();
    int run = ps - s + (w > 0 ? wsum[w - 1] : 0);
#pragma unroll
    for (int j = 0; j < 4; j++) {
        int i = base + j;
        if (i < N_NODES) g_off[i] = run;
        run += v[j];
    }
    if (t == 255) g_bsum[blk] = wsum[7];
}
__global__ void k_scan_top() {
    const int lane = threadIdx.x;
    const int nblk = (N_NODES + 1023) / 1024;
    int a = (lane < nblk) ? g_bsum[lane] : 0;
    int b = (lane + 32 < nblk) ? g_bsum[lane + 32] : 0;
    int pa = a;
#pragma unroll
    for (int o = 1; o < 32; o <<= 1) {
        int y = __shfl_up_sync(0xffffffffu, pa, o);
        if (lane >= o) pa += y;
    }
    int tot0 = __shfl_sync(0xffffffffu, pa, 31);
    int pb = b;
#pragma unroll
    for (int o = 1; o < 32; o <<= 1) {
        int y = __shfl_up_sync(0xffffffffu, pb, o);
        if (lane >= o) pb += y;
    }
    if (lane < nblk) g_bpre[lane] = pa - a;
    if (lane + 32 < nblk) g_bpre[lane + 32] = tot0 + pb - b;
}
__global__ void k_scan_add() {
    int i = blockIdx.x * blockDim.x + threadIdx.x;
    if (i < N_NODES) {
        int o = g_off[i] + g_bpre[i >> 10];
        g_off[i] = o;
        g_cur[i] = o;
    }
    if (i == 0) g_off[N_NODES] = N_EDGES;
}
__global__ void k_fill(const int* __restrict__ src, const int* __restrict__ dst) {
    int e = blockIdx.x * blockDim.x + threadIdx.x;
    if (e < N_EDGES) {
        int d = dst[e];
        int p = atomicAdd(&g_cur[d], 1);
        g_csr_src[p] = src[e];
    }
}

// ---------------- bf16 splits ------------------------------------------------
__global__ void k_split_x(const float* __restrict__ x) {
    int i = blockIdx.x * blockDim.x + threadIdx.x;
    const int total = N_NODES * NFEAT / 8;
    if (i >= total) return;
    const float4* p = (const float4*)x + (size_t)i * 2;
    float4 v0 = p[0], v1 = p[1];
    float f[8] = {v0.x, v0.y, v0.z, v0.w, v1.x, v1.y, v1.z, v1.w};
    __nv_bfloat16 hi[8], lo[8];
#pragma unroll
    for (int j = 0; j < 8; j++) {
        hi[j] = __float2bfloat16(f[j]);
        lo[j] = __float2bfloat16(f[j] - __bfloat162float(hi[j]));
    }
    *(uint4*)(g_xhi + (size_t)i * 8) = *(uint4*)hi;
    *(uint4*)(g_xlo + (size_t)i * 8) = *(uint4*)lo;
}
__global__ void k_split_w(const float* __restrict__ W1) {
    int idx = blockIdx.x * blockDim.x + threadIdx.x;
    if (idx >= F1 * NFEAT) return;
    int n = idx >> 9, k = idx & 511;
    int h = n >> 6, c = n & 63;
    float w = W1[((size_t)h * NFEAT + k) * NHID + c];
    __nv_bfloat16 hi = __float2bfloat16(w);
    __nv_bfloat16 lo = __float2bfloat16(w - __bfloat162float(hi));
    g_WThi[(size_t)n * NFEAT + k] = hi;
    g_WTlo[(size_t)n * NFEAT + k] = lo;
}
__global__ void k_split_w2(const float* __restrict__ W2) {
    int idx = blockIdx.x * blockDim.x + threadIdx.x;
    if (idx >= N2PAD * F1) return;
    int n = idx >> 9, k = idx & 511;
    float w = (n < NCLASS) ? W2[(size_t)k * NCLASS + n] : 0.f;
    __nv_bfloat16 hi = __float2bfloat16(w);
    __nv_bfloat16 lo = __float2bfloat16(w - __bfloat162float(hi));
    g_W2hi[(size_t)n * F1 + k] = hi;
    g_W2lo[(size_t)n * F1 + k] = lo;
}

// ---------------- GEMM1 (fused-split HMMA + fused scores) -------------------
// Grid: (bn=blockIdx.x in [0,4), bm=blockIdx.y in [0,391)) so consecutive CTAs
// share the same A row-panel through L2.
#define G1_BM     128
#define G1_BN     128
#define G1_KITER  16                 // 512 / 32
#define G1_ROWB   80
#define G1_REG    10240
#define G1_STAGE  (4 * G1_REG)       // 40960
#define G1_SMEM   (2 * G1_STAGE)     // 81920

__device__ __forceinline__ void g1_prefetch(int kb, uint32_t stage, int bm, int bn, int t) {
    const int k_in = kb * 32;
#pragma unroll
    for (int i = 0; i < 8; i++) {
        int q = t + i * 256;
        int region = q >> 9;          // 0:Ahi 1:Alo 2:Bhi 3:Blo
        int idx = q & 511;
        int row = idx >> 2, c = idx & 3;
        uint32_t dst = stage + region * G1_REG + row * G1_ROWB + c * 16;
        if (region < 2) {
            int grow = bm + row;
            int ok = grow < N_NODES;
            if (!ok) grow = 0;
            const __nv_bfloat16* Asrc = region ? g_xlo : g_xhi;
            const void* srcp = Asrc + (size_t)grow * NFEAT + k_in + c * 8;
            int sz = ok ? 16 : 0;
            asm volatile("cp.async.cg.shared.global [%0], [%1], 16, %2;"
                         :: "r"(dst), "l"(srcp), "r"(sz));
        } else {
            const __nv_bfloat16* Bsrc = (region == 3) ? g_WTlo : g_WThi;
            const void* srcp = Bsrc + (size_t)(bn + row) * NFEAT + k_in + c * 8;
            asm volatile("cp.async.cg.shared.global [%0], [%1], 16;"
                         :: "r"(dst), "l"(srcp));
        }
    }
}

__global__ __launch_bounds__(256, 2) void k_gemm1_mma(const float* __restrict__ a1) {
    extern __shared__ char dyn[];
    const uint32_t sbase = smem_u32(dyn);
    const int t    = threadIdx.x;
    const int wid  = t >> 5;
    const int lane = t & 31;
    const int bm   = blockIdx.y * G1_BM;
    const int bn   = blockIdx.x * G1_BN;
    const int mw   = (wid >> 2) * 64;
    const int nw   = (wid & 3) * 32;

    float acc[4][4][4];
#pragma unroll
    for (int mt = 0; mt < 4; mt++)
#pragma unroll
        for (int nt = 0; nt < 4; nt++)
#pragma unroll
            for (int j = 0; j < 4; j++) acc[mt][nt][j] = 0.f;

    g1_prefetch(0, sbase, bm, bn, t);
    asm volatile("cp.async.commit_group;");
    g1_prefetch(1, sbase + G1_STAGE, bm, bn, t);
    asm volatile("cp.async.commit_group;");

    const uint32_t a_off = (mw + (lane & 15)) * G1_ROWB + ((lane >> 4) * 16);
    const uint32_t b_off = (nw + (lane & 7) + ((lane >> 4) << 3)) * G1_ROWB + (((lane >> 3) & 1) * 16);

    for (int kb = 0; kb < G1_KITER; kb++) {
        asm volatile("cp.async.wait_group 1;");
        __syncthreads();
        const uint32_t stage = sbase + (kb & 1) * G1_STAGE;

#pragma unroll
        for (int ks = 0; ks < 2; ks++) {
            uint32_t ahi[4][4], alo[4][4];
#pragma unroll
            for (int mt = 0; mt < 4; mt++) {
                uint32_t ad = stage + a_off + mt * (16 * G1_ROWB) + ks * 32;
                LDSM_X4(ahi[mt][0], ahi[mt][1], ahi[mt][2], ahi[mt][3], ad);
                LDSM_X4(alo[mt][0], alo[mt][1], alo[mt][2], alo[mt][3], ad + G1_REG);
            }
            uint32_t b[2][4];
#pragma unroll
            for (int np = 0; np < 2; np++) {
                uint32_t bd = stage + 2 * G1_REG + b_off + np * (16 * G1_ROWB) + ks * 32;
                LDSM_X4(b[np][0], b[np][1], b[np][2], b[np][3], bd);
            }
#pragma unroll
            for (int mt = 0; mt < 4; mt++)
#pragma unroll
                for (int nt = 0; nt < 4; nt++) {
                    const uint32_t b0 = b[nt >> 1][(nt & 1) * 2];
                    const uint32_t b1 = b[nt >> 1][(nt & 1) * 2 + 1];
                    MMA16816(acc[mt][nt], ahi[mt], b0, b1);
                    MMA16816(acc[mt][nt], alo[mt], b0, b1);
                }
#pragma unroll
            for (int np = 0; np < 2; np++) {
                uint32_t bd = stage + 3 * G1_REG + b_off + np * (16 * G1_ROWB) + ks * 32;
                LDSM_X4(b[np][0], b[np][1], b[np][2], b[np][3], bd);
            }
#pragma unroll
            for (int mt = 0; mt < 4; mt++)
#pragma unroll
                for (int nt = 0; nt < 4; nt++) {
                    const uint32_t b0 = b[nt >> 1][(nt & 1) * 2];
                    const uint32_t b1 = b[nt >> 1][(nt & 1) * 2 + 1];
                    MMA16816(acc[mt][nt], ahi[mt], b0, b1);
                }
        }
        __syncthreads();
        if (kb + 2 < G1_KITER)
            g1_prefetch(kb + 2, stage, bm, bn, t);
        asm volatile("cp.async.commit_group;");
    }

    // epilogue: fp16 h1h + fused layer-1 attention scores
    const int r_base = bm + mw + (lane >> 2);
    const int hw = (bn + nw) >> 6;
    const int co0 = ((bn + nw) & 63) + (lane & 3) * 2;
#pragma unroll
    for (int mt = 0; mt < 4; mt++) {
#pragma unroll
        for (int nt = 0; nt < 4; nt++) {
            int r0 = r_base + mt * 16;
            int cc = bn + nw + (lane & 3) * 2 + nt * 8;
            if (r0 < N_NODES)
                *(__half2*)(g_h1h + (size_t)r0 * F1 + cc) = __floats2half2_rn(acc[mt][nt][0], acc[mt][nt][1]);
            if (r0 + 8 < N_NODES)
                *(__half2*)(g_h1h + (size_t)(r0 + 8) * F1 + cc) = __floats2half2_rn(acc[mt][nt][2], acc[mt][nt][3]);
        }
        float s0 = 0.f, d0 = 0.f, s1 = 0.f, d1 = 0.f;
#pragma unroll
        for (int nt = 0; nt < 4; nt++) {
#pragma unroll
            for (int je = 0; je < 2; je++) {
                int co = co0 + nt * 8 + je;
                float a_s = a1[hw * 128 + co];
                float a_d = a1[hw * 128 + 64 + co];
                s0 += acc[mt][nt][je] * a_s;
                d0 += acc[mt][nt][je] * a_d;
                s1 += acc[mt][nt][2 + je] * a_s;
                d1 += acc[mt][nt][2 + je] * a_d;
            }
        }
        s0 += __shfl_xor_sync(0xffffffffu, s0, 1); s0 += __shfl_xor_sync(0xffffffffu, s0, 2);
        d0 += __shfl_xor_sync(0xffffffffu, d0, 1); d0 += __shfl_xor_sync(0xffffffffu, d0, 2);
        s1 += __shfl_xor_sync(0xffffffffu, s1, 1); s1 += __shfl_xor_sync(0xffffffffu, s1, 2);
        d1 += __shfl_xor_sync(0xffffffffu, d1, 1); d1 += __shfl_xor_sync(0xffffffffu, d1, 2);
        if ((lane & 3) == 0) {
            int r0 = r_base + mt * 16;
            if (r0 < N_NODES) {
                atomicAdd(&g_s1s[r0 * NHEAD + hw], s0);
                atomicAdd(&g_s1d[r0 * NHEAD + hw], d0);
            }
            if (r0 + 8 < N_NODES) {
                atomicAdd(&g_s1s[(r0 + 8) * NHEAD + hw], s1);
                atomicAdd(&g_s1d[(r0 + 8) * NHEAD + hw], d1);
            }
        }
    }
}

// ---------------- GEMM2 (fused-split HMMA + fused layer-2 scores) -----------
#define G2_BM     128
#define G2_KITER  16
#define G2_AREG   10240
#define G2_BREG   5120
#define G2_STAGE  (2 * G2_AREG + 2 * G2_BREG)   // 30720
#define G2_SMEM   (2 * G2_STAGE)                // 61440

__device__ __forceinline__ void g2_prefetch(int kb, uint32_t stage, int bm, int t) {
    const int k_in = kb * 32;
#pragma unroll
    for (int i = 0; i < 6; i++) {
        int q = t + i * 256;
        if (q < 1024) {
            int region = q >> 9;
            int idx = q & 511;
            int row = idx >> 2, c = idx & 3;
            uint32_t dst = stage + region * G2_AREG + row * G1_ROWB + c * 16;
            int grow = bm + row;
            int ok = grow < N_NODES;
            if (!ok) grow = 0;
            const __nv_bfloat16* Asrc = region ? g_zlo : g_zhi;
            const void* srcp = Asrc + (size_t)grow * F1 + k_in + c * 8;
            int sz = ok ? 16 : 0;
            asm volatile("cp.async.cg.shared.global [%0], [%1], 16, %2;"
                         :: "r"(dst), "l"(srcp), "r"(sz));
        } else {
            int qb = q - 1024;
            int region = qb >> 8;
            int idx = qb & 255;
            int row = idx >> 2, c = idx & 3;
            uint32_t dst = stage + 2 * G2_AREG + region * G2_BREG + row * G1_ROWB + c * 16;
            const __nv_bfloat16* Bsrc = region ? g_W2lo : g_W2hi;
            const void* srcp = Bsrc + (size_t)row * F1 + k_in + c * 8;
            asm volatile("cp.async.cg.shared.global [%0], [%1], 16;"
                         :: "r"(dst), "l"(srcp));
        }
    }
}

__global__ __launch_bounds__(256, 2) void k_gemm2_mma(const float* __restrict__ a2) {
    extern __shared__ char dyn[];
    const uint32_t sbase = smem_u32(dyn);
    const int t    = threadIdx.x;
    const int wid  = t >> 5;
    const int lane = t & 31;
    const int bm   = blockIdx.x * G2_BM;
    const int mw   = (wid >> 1) * 32;
    const int nw   = (wid & 1) * 32;

    float acc[2][4][4];
#pragma unroll
    for (int mt = 0; mt < 2; mt++)
#pragma unroll
        for (int nt = 0; nt < 4; nt++)
#pragma unroll
            for (int j = 0; j < 4; j++) acc[mt][nt][j] = 0.f;

    g2_prefetch(0, sbase, bm, t);
    asm volatile("cp.async.commit_group;");
    g2_prefetch(1, sbase + G2_STAGE, bm, t);
    asm volatile("cp.async.commit_group;");

    const uint32_t a_off = (mw + (lane & 15)) * G1_ROWB + ((lane >> 4) * 16);
    const uint32_t b_off = (nw + (lane & 7) + ((lane >> 4) << 3)) * G1_ROWB + (((lane >> 3) & 1) * 16);

    for (int kb = 0; kb < G2_KITER; kb++) {
        asm volatile("cp.async.wait_group 1;");
        __syncthreads();
        const uint32_t stage = sbase + (kb & 1) * G2_STAGE;

#pragma unroll
        for (int ks = 0; ks < 2; ks++) {
            uint32_t ahi[2][4], alo[2][4];
#pragma unroll
            for (int mt = 0; mt < 2; mt++) {
                uint32_t ad = stage + a_off + mt * (16 * G1_ROWB) + ks * 32;
                LDSM_X4(ahi[mt][0], ahi[mt][1], ahi[mt][2], ahi[mt][3], ad);
                LDSM_X4(alo[mt][0], alo[mt][1], alo[mt][2], alo[mt][3], ad + G2_AREG);
            }
            uint32_t b[2][4];
#pragma unroll
            for (int np = 0; np < 2; np++) {
                uint32_t bd = stage + 2 * G2_AREG + b_off + np * (16 * G1_ROWB) + ks * 32;
                LDSM_X4(b[np][0], b[np][1], b[np][2], b[np][3], bd);
            }
#pragma unroll
            for (int mt = 0; mt < 2; mt++)
#pragma unroll
                for (int nt = 0; nt < 4; nt++) {
                    const uint32_t b0 = b[nt >> 1][(nt & 1) * 2];
                    const uint32_t b1 = b[nt >> 1][(nt & 1) * 2 + 1];
                    MMA16816(acc[mt][nt], ahi[mt], b0, b1);
                    MMA16816(acc[mt][nt], alo[mt], b0, b1);
                }
#pragma unroll
            for (int np = 0; np < 2; np++) {
                uint32_t bd = stage + 2 * G2_AREG + G2_BREG + b_off + np * (16 * G1_ROWB) + ks * 32;
                LDSM_X4(b[np][0], b[np][1], b[np][2], b[np][3], bd);
            }
#pragma unroll
            for (int mt = 0; mt < 2; mt++)
#pragma unroll
                for (int nt = 0; nt < 4; nt++) {
                    const uint32_t b0 = b[nt >> 1][(nt & 1) * 2];
                    const uint32_t b1 = b[nt >> 1][(nt & 1) * 2 + 1];
                    MMA16816(acc[mt][nt], ahi[mt], b0, b1);
                }
        }
        __syncthreads();
        if (kb + 2 < G2_KITER)
            g2_prefetch(kb + 2, stage, bm, t);
        asm volatile("cp.async.commit_group;");
    }

    // epilogue: h2 store + fused layer-2 scores
    const int r_base = bm + mw + (lane >> 2);
    const int c_base = nw + (lane & 3) * 2;
#pragma unroll
    for (int mt = 0; mt < 2; mt++) {
#pragma unroll
        for (int nt = 0; nt < 4; nt++) {
            int r0 = r_base + mt * 16;
            int cc = c_base + nt * 8;
            if (cc < NCLASS) {
                if (r0 < N_NODES)
                    *(float2*)(g_h2 + (size_t)r0 * NCLASS + cc) = make_float2(acc[mt][nt][0], acc[mt][nt][1]);
                if (r0 + 8 < N_NODES)
                    *(float2*)(g_h2 + (size_t)(r0 + 8) * NCLASS + cc) = make_float2(acc[mt][nt][2], acc[mt][nt][3]);
            }
        }
    }
#pragma unroll
    for (int mt = 0; mt < 2; mt++) {
        float s0 = 0.f, d0 = 0.f, s1 = 0.f, d1 = 0.f;
#pragma unroll
        for (int nt = 0; nt < 4; nt++) {
#pragma unroll
            for (int je = 0; je < 2; je++) {
                int cc = c_base + nt * 8 + je;
                float a_s = (cc < NCLASS) ? a2[cc] : 0.f;
                float a_d = (cc < NCLASS) ? a2[NCLASS + cc] : 0.f;
                s0 += acc[mt][nt][je] * a_s;
                d0 += acc[mt][nt][je] * a_d;
                s1 += acc[mt][nt][2 + je] * a_s;
                d1 += acc[mt][nt][2 + je] * a_d;
            }
        }
        s0 += __shfl_xor_sync(0xffffffffu, s0, 1); s0 += __shfl_xor_sync(0xffffffffu, s0, 2);
        d0 += __shfl_xor_sync(0xffffffffu, d0, 1); d0 += __shfl_xor_sync(0xffffffffu, d0, 2);
        s1 += __shfl_xor_sync(0xffffffffu, s1, 1); s1 += __shfl_xor_sync(0xffffffffu, s1, 2);
        d1 += __shfl_xor_sync(0xffffffffu, d1, 1); d1 += __shfl_xor_sync(0xffffffffu, d1, 2);
        if ((lane & 3) == 0) {
            int r0 = r_base + mt * 16;
            if (r0 < N_NODES) {
                atomicAdd(&g_s2s[r0], s0);
                atomicAdd(&g_s2d[r0], d0);
            }
            if (r0 + 8 < N_NODES) {
                atomicAdd(&g_s2s[r0 + 8], s1);
                atomicAdd(&g_s2d[r0 + 8], d1);
            }
        }
    }
}

__device__ __forceinline__ float lrelu(float x) { return x > 0.f ? x : NEG * x; }

// ---------------- layer-1 softmax-aggregate (fp16 gather, split bf16 out) ---
__global__ __launch_bounds__(256) void k_agg1(const float* __restrict__ b1) {
    int n    = (blockIdx.x * blockDim.x + threadIdx.x) >> 5;
    int lane = threadIdx.x & 31;
    if (n >= N_NODES) return;
    const int beg = g_off[n], end = g_off[n + 1];

    const int h  = lane & 7;
    const int es = lane >> 3;
    const float sdh = g_s1d[n * NHEAD + h];

    float m = -1e30f;
    for (int i = beg + es; i < end; i += 4) {
        int s = g_csr_src[i];
        float e = lrelu(g_s1s[s * NHEAD + h] + sdh);
        m = fmaxf(m, e);
    }
    m = fmaxf(m, __shfl_xor_sync(0xffffffffu, m, 8));
    m = fmaxf(m, __shfl_xor_sync(0xffffffffu, m, 16));

    float den = 0.f;
    for (int i = beg + es; i < end; i += 4) {
        int s = g_csr_src[i];
        float e = lrelu(g_s1s[s * NHEAD + h] + sdh);
        den += __expf(e - m);
    }
    den += __shfl_xor_sync(0xffffffffu, den, 8);
    den += __shfl_xor_sync(0xffffffffu, den, 16);
    den = fmaxf(den, 1e-16f);

    float acc[16];
#pragma unroll
    for (int j = 0; j < 16; j++) acc[j] = 0.f;
    const int hl = lane >> 2;

    for (int i = beg; i < end; i++) {
        int s = g_csr_src[i];
        float alpha = 0.f;
        if (lane < 8) {
            float e = lrelu(g_s1s[s * NHEAD + lane] + sdh);
            alpha = __expf(e - m) / den;
        }
        alpha = __shfl_sync(0xffffffffu, alpha, hl);
        const uint4* hp = (const uint4*)(g_h1h + (size_t)s * F1 + lane * 16);
        uint4 q0 = hp[0];
        uint4 q1 = hp[1];
        float2 f;
        f = __half22float2(*(__half2*)&q0.x); acc[0] += alpha * f.x; acc[1] += alpha * f.y;
        f = __half22float2(*(__half2*)&q0.y); acc[2] += alpha * f.x; acc[3] += alpha * f.y;
        f = __half22float2(*(__half2*)&q0.z); acc[4] += alpha * f.x; acc[5] += alpha * f.y;
        f = __half22float2(*(__half2*)&q0.w); acc[6] += alpha * f.x; acc[7] += alpha * f.y;
        f = __half22float2(*(__half2*)&q1.x); acc[8] += alpha * f.x; acc[9] += alpha * f.y;
        f = __half22float2(*(__half2*)&q1.y); acc[10] += alpha * f.x; acc[11] += alpha * f.y;
        f = __half22float2(*(__half2*)&q1.z); acc[12] += alpha * f.x; acc[13] += alpha * f.y;
        f = __half22float2(*(__half2*)&q1.w); acc[14] += alpha * f.x; acc[15] += alpha * f.y;
    }

    const float4* bp = (const float4*)(b1 + lane * 16);
#pragma unroll
    for (int j = 0; j < 4; j++) {
        float4 b = bp[j];
        float v[4];
        v[0] = acc[j * 4 + 0] + b.x;
        v[1] = acc[j * 4 + 1] + b.y;
        v[2] = acc[j * 4 + 2] + b.z;
        v[3] = acc[j * 4 + 3] + b.w;
        __nv_bfloat16 hi[4], lo[4];
#pragma unroll
        for (int q = 0; q < 4; q++) {
            float e = v[q] > 0.f ? v[q] : expm1f(v[q]);
            hi[q] = __float2bfloat16(e);
            lo[q] = __float2bfloat16(e - __bfloat162float(hi[q]));
        }
        *(uint2*)(g_zhi + (size_t)n * F1 + lane * 16 + j * 4) = *(uint2*)hi;
        *(uint2*)(g_zlo + (size_t)n * F1 + lane * 16 + j * 4) = *(uint2*)lo;
    }
}

// ---------------- layer-2 aggregate + bias + log_softmax --------------------
__global__ __launch_bounds__(256) void k_agg2(const float* __restrict__ b2,
                                              float* __restrict__ out) {
    int n    = (blockIdx.x * blockDim.x + threadIdx.x) >> 5;
    int lane = threadIdx.x & 31;
    if (n >= N_NODES) return;
    const int beg = g_off[n], end = g_off[n + 1];
    const float sdn = g_s2d[n];

    float m = -1e30f;
    for (int i = beg + lane; i < end; i += 32) {
        int s = g_csr_src[i];
        m = fmaxf(m, lrelu(g_s2s[s] + sdn));
    }
#pragma unroll
    for (int off = 16; off > 0; off >>= 1)
        m = fmaxf(m, __shfl_xor_sync(0xffffffffu, m, off));

    float den = 0.f;
    for (int i = beg + lane; i < end; i += 32) {
        int s = g_csr_src[i];
        den += __expf(lrelu(g_s2s[s] + sdn) - m);
    }
#pragma unroll
    for (int off = 16; off > 0; off >>= 1)
        den += __shfl_xor_sync(0xffffffffu, den, off);
    den = fmaxf(den, 1e-16f);

    float acc0 = 0.f, acc1 = 0.f;
    for (int i = beg; i < end; i++) {
        int s = g_csr_src[i];
        float e = lrelu(g_s2s[s] + sdn);
        float alpha = __expf(e - m) / den;
        acc0 += alpha * g_h2[(size_t)s * NCLASS + lane];
        if (lane < 8) acc1 += alpha * g_h2[(size_t)s * NCLASS + 32 + lane];
    }

    float v0 = acc0 + b2[lane];
    float v1 = (lane < 8) ? (acc1 + b2[32 + lane]) : -1e30f;

    float mx = fmaxf(v0, v1);
#pragma unroll
    for (int off = 16; off > 0; off >>= 1)
        mx = fmaxf(mx, __shfl_xor_sync(0xffffffffu, mx, off));
    float se = __expf(v0 - mx) + ((lane < 8) ? __expf(v1 - mx) : 0.f);
#pragma unroll
    for (int off = 16; off > 0; off >>= 1)
        se += __shfl_xor_sync(0xffffffffu, se, off);
    float ls = logf(se);

    out[(size_t)n * NCLASS + lane] = v0 - mx - ls;
    if (lane < 8) out[(size_t)n * NCLASS + 32 + lane] = v1 - mx - ls;
}

// ---------------- launch -----------------------------------------------------
extern "C" void kernel_launch(void* const* d_in, const int* in_sizes, int n_in,
                              void* d_out, int out_size) {
    const float* x  = (const float*)d_in[0];
    const int*   el = (const int*)d_in[1];
    const float* W1 = (const float*)d_in[2];
    const float* a1 = (const float*)d_in[3];
    const float* b1 = (const float*)d_in[4];
    const float* W2 = (const float*)d_in[5];
    const float* a2 = (const float*)d_in[6];
    const float* b2 = (const float*)d_in[7];
    float* out = (float*)d_out;

    const int* src = el;
    const int* dst = el + N_EDGES;

    static cudaStream_t s2 = nullptr;
    static cudaEvent_t ev_fork = nullptr, ev_join = nullptr;
    if (!s2) {
        cudaStreamCreateWithFlags(&s2, cudaStreamNonBlocking);
        cudaEventCreateWithFlags(&ev_fork, cudaEventDisableTiming);
        cudaEventCreateWithFlags(&ev_join, cudaEventDisableTiming);
        cudaFuncSetAttribute(k_gemm1_mma, cudaFuncAttributeMaxDynamicSharedMemorySize, G1_SMEM);
        cudaFuncSetAttribute(k_gemm2_mma, cudaFuncAttributeMaxDynamicSharedMemorySize, G2_SMEM);
    }

    const int TB = 256;
    const int NBLK = (N_NODES + 1023) / 1024;

    // fork FIRST: CSR build is independent of the GEMM path and runs alongside it
    cudaEventRecord(ev_fork, 0);
    cudaStreamWaitEvent(s2, ev_fork, 0);

    // main stream: split + zero + gemm1 (gemm1 = submission index 3 for ncu)
    k_split_x<<<(N_NODES * NFEAT / 8 + TB - 1) / TB, TB>>>(x);                    // 0
    k_split_w<<<(F1 * NFEAT + TB - 1) / TB, TB>>>(W1);                            // 1
    k_zero_scores<<<(N_NODES * NHEAD + TB - 1) / TB, TB>>>();                     // 2
    k_gemm1_mma<<<dim3(F1 / G1_BN, (N_NODES + G1_BM - 1) / G1_BM), 256, G1_SMEM>>>(a1); // 3

    // side stream: CSR build + W2 split (runs concurrently with the above)
    k_zero_deg<<<(N_NODES + TB - 1) / TB, TB, 0, s2>>>();
    k_count<<<(N_EDGES + TB - 1) / TB, TB, 0, s2>>>(dst);
    k_scan_blk<<<NBLK, 256, 0, s2>>>();
    k_scan_top<<<1, 32, 0, s2>>>();
    k_scan_add<<<(N_NODES + TB - 1) / TB, TB, 0, s2>>>();
    k_fill<<<(N_EDGES + TB - 1) / TB, TB, 0, s2>>>(src, dst);
    k_split_w2<<<(N2PAD * F1 + TB - 1) / TB, TB, 0, s2>>>(W2);
    cudaEventRecord(ev_join, s2);

    // main stream rejoins, then the dependent chain
    cudaStreamWaitEvent(0, ev_join, 0);
    k_agg1<<<(N_NODES + 7) / 8, 256>>>(b1);
    k_gemm2_mma<<<(N_NODES + G2_BM - 1) / G2_BM, 256, G2_SMEM>>>(a2);
    k_agg2<<<(N_NODES + 7) / 8, 256>>>(b2, out);
}

// round 14
// speedup vs baseline: 1.4698x; 1.3626x over previous
#include <cuda_runtime.h>
#include <cuda_bf16.h>
#include <cuda_fp16.h>
#include <cstdint>

#define N_NODES 50000
#define N_EDGES 800000
#define NFEAT   512
#define NHID    64
#define NHEAD   8
#define F1      512      // NHEAD*NHID
#define NCLASS  40
#define N2PAD   64
#define NEG     0.2f

// ---------------- scratch ---------------------------------------------------
__device__ __half g_h1h[(size_t)N_NODES * F1];   // fp16 gather copy of h1
__device__ float g_h2[(size_t)N_NODES * NCLASS];
__device__ float g_s1s[N_NODES * NHEAD];
__device__ float g_s1d[N_NODES * NHEAD];
__device__ float g_s2s[N_NODES];
__device__ float g_s2d[N_NODES];
__device__ int   g_deg[N_NODES];
__device__ int   g_off[N_NODES + 1];
__device__ int   g_cur[N_NODES];
__device__ int   g_csr_src[N_EDGES];
__device__ int   g_bsum[64];
__device__ int   g_bpre[64];
// fp16 operands for gemm1 (1-term)
__device__ __half g_xh [(size_t)N_NODES * NFEAT];
__device__ __half g_WTh[F1 * NFEAT];             // [n][k], n = h*64+c
// bf16 split operands for gemm2
__device__ __nv_bfloat16 g_zhi[(size_t)N_NODES * F1];
__device__ __nv_bfloat16 g_zlo[(size_t)N_NODES * F1];
__device__ __nv_bfloat16 g_W2hi[N2PAD * F1];
__device__ __nv_bfloat16 g_W2lo[N2PAD * F1];

__device__ __forceinline__ uint32_t smem_u32(const void* p) {
    uint32_t a;
    asm("{ .reg .u64 t; cvta.to.shared.u64 t, %1; cvt.u32.u64 %0, t; }" : "=r"(a) : "l"(p));
    return a;
}

#define LDSM_X4(r0, r1, r2, r3, addr) \
    asm volatile("ldmatrix.sync.aligned.m8n8.x4.shared.b16 {%0,%1,%2,%3}, [%4];" \
                 : "=r"(r0), "=r"(r1), "=r"(r2), "=r"(r3) : "r"(addr))
#define MMA16816(acc, a, b0, b1) \
    asm volatile("mma.sync.aligned.m16n8k16.row.col.f32.bf16.bf16.f32 " \
                 "{%0,%1,%2,%3}, {%4,%5,%6,%7}, {%8,%9}, {%0,%1,%2,%3};" \
                 : "+f"((acc)[0]), "+f"((acc)[1]), "+f"((acc)[2]), "+f"((acc)[3]) \
                 : "r"((a)[0]), "r"((a)[1]), "r"((a)[2]), "r"((a)[3]), "r"(b0), "r"(b1))
#define MMA16816H(acc, a, b0, b1) \
    asm volatile("mma.sync.aligned.m16n8k16.row.col.f32.f16.f16.f32 " \
                 "{%0,%1,%2,%3}, {%4,%5,%6,%7}, {%8,%9}, {%0,%1,%2,%3};" \
                 : "+f"((acc)[0]), "+f"((acc)[1]), "+f"((acc)[2]), "+f"((acc)[3]) \
                 : "r"((a)[0]), "r"((a)[1]), "r"((a)[2]), "r"((a)[3]), "r"(b0), "r"(b1))

// ---------------- CSR construction ------------------------------------------
__global__ void k_zero_deg() {
    int i = blockIdx.x * blockDim.x + threadIdx.x;
    if (i < N_NODES) g_deg[i] = 0;
}
__global__ void k_zero_scores() {
    int i = blockIdx.x * blockDim.x + threadIdx.x;
    if (i < N_NODES * NHEAD) {
        g_s1s[i] = 0.f;
        g_s1d[i] = 0.f;
    }
    if (i < N_NODES) {
        g_s2s[i] = 0.f;
        g_s2d[i] = 0.f;
    }
}
__global__ void k_count(const int* __restrict__ dst) {
    int e = blockIdx.x * blockDim.x + threadIdx.x;
    if (e < N_EDGES) atomicAdd(&g_deg[dst[e]], 1);
}
__global__ __launch_bounds__(256) void k_scan_blk() {
    __shared__ int wsum[8];
    const int blk = blockIdx.x, t = threadIdx.x;
    const int base = blk * 1024 + t * 4;
    int v[4], s = 0;
#pragma unroll
    for (int j = 0; j < 4; j++) {
        int i = base + j;
        v[j] = (i < N_NODES) ? g_deg[i] : 0;
        s += v[j];
    }
    const int lane = t & 31, w = t >> 5;
    int ps = s;
#pragma unroll
    for (int o = 1; o < 32; o <<= 1) {
        int y = __shfl_up_sync(0xffffffffu, ps, o);
        if (lane >= o) ps += y;
    }
    if (lane == 31) wsum[w] = ps;
    __syncthreads();
    if (w == 0) {
        int ws = (lane < 8) ? wsum[lane] : 0;
#pragma unroll
        for (int o = 1; o < 8; o <<= 1) {
            int y = __shfl_up_sync(0xffffffffu, ws, o);
            if (lane >= o) ws += y;
        }
        if (lane < 8) wsum[lane] = ws;
    }
    __syncthreads();
    int run = ps - s + (w > 0 ? wsum[w - 1] : 0);
#pragma unroll
    for (int j = 0; j < 4; j++) {
        int i = base + j;
        if (i < N_NODES) g_off[i] = run;
        run += v[j];
    }
    if (t == 255) g_bsum[blk] = wsum[7];
}
__global__ void k_scan_top() {
    const int lane = threadIdx.x;
    const int nblk = (N_NODES + 1023) / 1024;
    int a = (lane < nblk) ? g_bsum[lane] : 0;
    int b = (lane + 32 < nblk) ? g_bsum[lane + 32] : 0;
    int pa = a;
#pragma unroll
    for (int o = 1; o < 32; o <<= 1) {
        int y = __shfl_up_sync(0xffffffffu, pa, o);
        if (lane >= o) pa += y;
    }
    int tot0 = __shfl_sync(0xffffffffu, pa, 31);
    int pb = b;
#pragma unroll
    for (int o = 1; o < 32; o <<= 1) {
        int y = __shfl_up_sync(0xffffffffu, pb, o);
        if (lane >= o) pb += y;
    }
    if (lane < nblk) g_bpre[lane] = pa - a;
    if (lane + 32 < nblk) g_bpre[lane + 32] = tot0 + pb - b;
}
__global__ void k_scan_add() {
    int i = blockIdx.x * blockDim.x + threadIdx.x;
    if (i < N_NODES) {
        int o = g_off[i] + g_bpre[i >> 10];
        g_off[i] = o;
        g_cur[i] = o;
    }
    if (i == 0) g_off[N_NODES] = N_EDGES;
}
__global__ void k_fill(const int* __restrict__ src, const int* __restrict__ dst) {
    int e = blockIdx.x * blockDim.x + threadIdx.x;
    if (e < N_EDGES) {
        int d = dst[e];
        int p = atomicAdd(&g_cur[d], 1);
        g_csr_src[p] = src[e];
    }
}

// ---------------- operand conversion -----------------------------------------
__global__ void k_split_x(const float* __restrict__ x) {
    int i = blockIdx.x * blockDim.x + threadIdx.x;
    const int total = N_NODES * NFEAT / 8;
    if (i >= total) return;
    const float4* p = (const float4*)x + (size_t)i * 2;
    float4 v0 = p[0], v1 = p[1];
    __half h[8];
    h[0] = __float2half(v0.x); h[1] = __float2half(v0.y);
    h[2] = __float2half(v0.z); h[3] = __float2half(v0.w);
    h[4] = __float2half(v1.x); h[5] = __float2half(v1.y);
    h[6] = __float2half(v1.z); h[7] = __float2half(v1.w);
    *(uint4*)(g_xh + (size_t)i * 8) = *(uint4*)h;
}
__global__ void k_split_w(const float* __restrict__ W1) {
    int idx = blockIdx.x * blockDim.x + threadIdx.x;
    if (idx >= F1 * NFEAT) return;
    int n = idx >> 9, k = idx & 511;
    int h = n >> 6, c = n & 63;
    g_WTh[(size_t)n * NFEAT + k] = __float2half(W1[((size_t)h * NFEAT + k) * NHID + c]);
}
__global__ void k_split_w2(const float* __restrict__ W2) {
    int idx = blockIdx.x * blockDim.x + threadIdx.x;
    if (idx >= N2PAD * F1) return;
    int n = idx >> 9, k = idx & 511;
    float w = (n < NCLASS) ? W2[(size_t)k * NCLASS + n] : 0.f;
    __nv_bfloat16 hi = __float2bfloat16(w);
    __nv_bfloat16 lo = __float2bfloat16(w - __bfloat162float(hi));
    g_W2hi[(size_t)n * F1 + k] = hi;
    g_W2lo[(size_t)n * F1 + k] = lo;
}

// ---------------- GEMM1 (pure fp16 HMMA + fused scores) ----------------------
// 1-term fp16: h1 = x_f16 @ Wt_f16, fp32 accum. CTA 128x128, 8 warps 64x32,
// 3-stage cp.async pipe, 2 CTAs/SM. Grid (bn, bm) N-major for L2 A-sharing.
#define G1_BM     128
#define G1_BN     128
#define G1_KITER  16                 // 512 / 32
#define G1_ROWB   80
#define G1_REG    10240
#define G1_STAGE  (2 * G1_REG)       // A | B = 20480
#define G1_NSTG   3
#define G1_SMEM   (G1_NSTG * G1_STAGE)   // 61440

__device__ __forceinline__ void g1_prefetch(int kb, uint32_t stage, int bm, int bn, int t) {
    const int k_in = kb * 32;
#pragma unroll
    for (int i = 0; i < 4; i++) {
        int q = t + i * 256;
        int region = q >> 9;          // 0:A 1:B
        int idx = q & 511;
        int row = idx >> 2, c = idx & 3;
        uint32_t dst = stage + region * G1_REG + row * G1_ROWB + c * 16;
        if (region == 0) {
            int grow = bm + row;
            int ok = grow < N_NODES;
            if (!ok) grow = 0;
            const void* srcp = g_xh + (size_t)grow * NFEAT + k_in + c * 8;
            int sz = ok ? 16 : 0;
            asm volatile("cp.async.cg.shared.global [%0], [%1], 16, %2;"
                         :: "r"(dst), "l"(srcp), "r"(sz));
        } else {
            const void* srcp = g_WTh + (size_t)(bn + row) * NFEAT + k_in + c * 8;
            asm volatile("cp.async.cg.shared.global [%0], [%1], 16;"
                         :: "r"(dst), "l"(srcp));
        }
    }
}

__global__ __launch_bounds__(256, 2) void k_gemm1_mma(const float* __restrict__ a1) {
    extern __shared__ char dyn[];
    const uint32_t sbase = smem_u32(dyn);
    const int t    = threadIdx.x;
    const int wid  = t >> 5;
    const int lane = t & 31;
    const int bm   = blockIdx.y * G1_BM;
    const int bn   = blockIdx.x * G1_BN;
    const int mw   = (wid >> 2) * 64;
    const int nw   = (wid & 3) * 32;

    float acc[4][4][4];
#pragma unroll
    for (int mt = 0; mt < 4; mt++)
#pragma unroll
        for (int nt = 0; nt < 4; nt++)
#pragma unroll
            for (int j = 0; j < 4; j++) acc[mt][nt][j] = 0.f;

    g1_prefetch(0, sbase, bm, bn, t);
    asm volatile("cp.async.commit_group;");
    g1_prefetch(1, sbase + G1_STAGE, bm, bn, t);
    asm volatile("cp.async.commit_group;");
    g1_prefetch(2, sbase + 2 * G1_STAGE, bm, bn, t);
    asm volatile("cp.async.commit_group;");

    const uint32_t a_off = (mw + (lane & 15)) * G1_ROWB + ((lane >> 4) * 16);
    const uint32_t b_off = G1_REG + (nw + (lane & 7) + ((lane >> 4) << 3)) * G1_ROWB + (((lane >> 3) & 1) * 16);

    int st = 0;
    for (int kb = 0; kb < G1_KITER; kb++) {
        asm volatile("cp.async.wait_group 2;");
        __syncthreads();
        const uint32_t stage = sbase + st * G1_STAGE;

#pragma unroll
        for (int ks = 0; ks < 2; ks++) {
            uint32_t a[4][4];
#pragma unroll
            for (int mt = 0; mt < 4; mt++) {
                uint32_t ad = stage + a_off + mt * (16 * G1_ROWB) + ks * 32;
                LDSM_X4(a[mt][0], a[mt][1], a[mt][2], a[mt][3], ad);
            }
            uint32_t b[2][4];
#pragma unroll
            for (int np = 0; np < 2; np++) {
                uint32_t bd = stage + b_off + np * (16 * G1_ROWB) + ks * 32;
                LDSM_X4(b[np][0], b[np][1], b[np][2], b[np][3], bd);
            }
#pragma unroll
            for (int mt = 0; mt < 4; mt++)
#pragma unroll
                for (int nt = 0; nt < 4; nt++) {
                    const uint32_t b0 = b[nt >> 1][(nt & 1) * 2];
                    const uint32_t b1 = b[nt >> 1][(nt & 1) * 2 + 1];
                    MMA16816H(acc[mt][nt], a[mt], b0, b1);
                }
        }
        __syncthreads();
        if (kb + G1_NSTG < G1_KITER)
            g1_prefetch(kb + G1_NSTG, stage, bm, bn, t);
        asm volatile("cp.async.commit_group;");
        st = (st == G1_NSTG - 1) ? 0 : st + 1;
    }

    // epilogue: fp16 h1h + fused layer-1 attention scores
    const int r_base = bm + mw + (lane >> 2);
    const int hw = (bn + nw) >> 6;
    const int co0 = ((bn + nw) & 63) + (lane & 3) * 2;
#pragma unroll
    for (int mt = 0; mt < 4; mt++) {
#pragma unroll
        for (int nt = 0; nt < 4; nt++) {
            int r0 = r_base + mt * 16;
            int cc = bn + nw + (lane & 3) * 2 + nt * 8;
            if (r0 < N_NODES)
                *(__half2*)(g_h1h + (size_t)r0 * F1 + cc) = __floats2half2_rn(acc[mt][nt][0], acc[mt][nt][1]);
            if (r0 + 8 < N_NODES)
                *(__half2*)(g_h1h + (size_t)(r0 + 8) * F1 + cc) = __floats2half2_rn(acc[mt][nt][2], acc[mt][nt][3]);
        }
        float s0 = 0.f, d0 = 0.f, s1 = 0.f, d1 = 0.f;
#pragma unroll
        for (int nt = 0; nt < 4; nt++) {
#pragma unroll
            for (int je = 0; je < 2; je++) {
                int co = co0 + nt * 8 + je;
                float a_s = a1[hw * 128 + co];
                float a_d = a1[hw * 128 + 64 + co];
                s0 += acc[mt][nt][je] * a_s;
                d0 += acc[mt][nt][je] * a_d;
                s1 += acc[mt][nt][2 + je] * a_s;
                d1 += acc[mt][nt][2 + je] * a_d;
            }
        }
        s0 += __shfl_xor_sync(0xffffffffu, s0, 1); s0 += __shfl_xor_sync(0xffffffffu, s0, 2);
        d0 += __shfl_xor_sync(0xffffffffu, d0, 1); d0 += __shfl_xor_sync(0xffffffffu, d0, 2);
        s1 += __shfl_xor_sync(0xffffffffu, s1, 1); s1 += __shfl_xor_sync(0xffffffffu, s1, 2);
        d1 += __shfl_xor_sync(0xffffffffu, d1, 1); d1 += __shfl_xor_sync(0xffffffffu, d1, 2);
        if ((lane & 3) == 0) {
            int r0 = r_base + mt * 16;
            if (r0 < N_NODES) {
                atomicAdd(&g_s1s[r0 * NHEAD + hw], s0);
                atomicAdd(&g_s1d[r0 * NHEAD + hw], d0);
            }
            if (r0 + 8 < N_NODES) {
                atomicAdd(&g_s1s[(r0 + 8) * NHEAD + hw], s1);
                atomicAdd(&g_s1d[(r0 + 8) * NHEAD + hw], d1);
            }
        }
    }
}

// ---------------- GEMM2 (fused-split HMMA + fused layer-2 scores) -----------
#define G2_BM     128
#define G2_KITER  16
#define G2_AREG   10240
#define G2_BREG   5120
#define G2_STAGE  (2 * G2_AREG + 2 * G2_BREG)   // 30720
#define G2_SMEM   (2 * G2_STAGE)                // 61440

__device__ __forceinline__ void g2_prefetch(int kb, uint32_t stage, int bm, int t) {
    const int k_in = kb * 32;
#pragma unroll
    for (int i = 0; i < 6; i++) {
        int q = t + i * 256;
        if (q < 1024) {
            int region = q >> 9;
            int idx = q & 511;
            int row = idx >> 2, c = idx & 3;
            uint32_t dst = stage + region * G2_AREG + row * G1_ROWB + c * 16;
            int grow = bm + row;
            int ok = grow < N_NODES;
            if (!ok) grow = 0;
            const __nv_bfloat16* Asrc = region ? g_zlo : g_zhi;
            const void* srcp = Asrc + (size_t)grow * F1 + k_in + c * 8;
            int sz = ok ? 16 : 0;
            asm volatile("cp.async.cg.shared.global [%0], [%1], 16, %2;"
                         :: "r"(dst), "l"(srcp), "r"(sz));
        } else {
            int qb = q - 1024;
            int region = qb >> 8;
            int idx = qb & 255;
            int row = idx >> 2, c = idx & 3;
            uint32_t dst = stage + 2 * G2_AREG + region * G2_BREG + row * G1_ROWB + c * 16;
            const __nv_bfloat16* Bsrc = region ? g_W2lo : g_W2hi;
            const void* srcp = Bsrc + (size_t)row * F1 + k_in + c * 8;
            asm volatile("cp.async.cg.shared.global [%0], [%1], 16;"
                         :: "r"(dst), "l"(srcp));
        }
    }
}

__global__ __launch_bounds__(256, 2) void k_gemm2_mma(const float* __restrict__ a2) {
    extern __shared__ char dyn[];
    const uint32_t sbase = smem_u32(dyn);
    const int t    = threadIdx.x;
    const int wid  = t >> 5;
    const int lane = t & 31;
    const int bm   = blockIdx.x * G2_BM;
    const int mw   = (wid >> 1) * 32;
    const int nw   = (wid & 1) * 32;

    float acc[2][4][4];
#pragma unroll
    for (int mt = 0; mt < 2; mt++)
#pragma unroll
        for (int nt = 0; nt < 4; nt++)
#pragma unroll
            for (int j = 0; j < 4; j++) acc[mt][nt][j] = 0.f;

    g2_prefetch(0, sbase, bm, t);
    asm volatile("cp.async.commit_group;");
    g2_prefetch(1, sbase + G2_STAGE, bm, t);
    asm volatile("cp.async.commit_group;");

    const uint32_t a_off = (mw + (lane & 15)) * G1_ROWB + ((lane >> 4) * 16);
    const uint32_t b_off = (nw + (lane & 7) + ((lane >> 4) << 3)) * G1_ROWB + (((lane >> 3) & 1) * 16);

    for (int kb = 0; kb < G2_KITER; kb++) {
        asm volatile("cp.async.wait_group 1;");
        __syncthreads();
        const uint32_t stage = sbase + (kb & 1) * G2_STAGE;

#pragma unroll
        for (int ks = 0; ks < 2; ks++) {
            uint32_t ahi[2][4], alo[2][4];
#pragma unroll
            for (int mt = 0; mt < 2; mt++) {
                uint32_t ad = stage + a_off + mt * (16 * G1_ROWB) + ks * 32;
                LDSM_X4(ahi[mt][0], ahi[mt][1], ahi[mt][2], ahi[mt][3], ad);
                LDSM_X4(alo[mt][0], alo[mt][1], alo[mt][2], alo[mt][3], ad + G2_AREG);
            }
            uint32_t b[2][4];
#pragma unroll
            for (int np = 0; np < 2; np++) {
                uint32_t bd = stage + 2 * G2_AREG + b_off + np * (16 * G1_ROWB) + ks * 32;
                LDSM_X4(b[np][0], b[np][1], b[np][2], b[np][3], bd);
            }
#pragma unroll
            for (int mt = 0; mt < 2; mt++)
#pragma unroll
                for (int nt = 0; nt < 4; nt++) {
                    const uint32_t b0 = b[nt >> 1][(nt & 1) * 2];
                    const uint32_t b1 = b[nt >> 1][(nt & 1) * 2 + 1];
                    MMA16816(acc[mt][nt], ahi[mt], b0, b1);
                    MMA16816(acc[mt][nt], alo[mt], b0, b1);
                }
#pragma unroll
            for (int np = 0; np < 2; np++) {
                uint32_t bd = stage + 2 * G2_AREG + G2_BREG + b_off + np * (16 * G1_ROWB) + ks * 32;
                LDSM_X4(b[np][0], b[np][1], b[np][2], b[np][3], bd);
            }
#pragma unroll
            for (int mt = 0; mt < 2; mt++)
#pragma unroll
                for (int nt = 0; nt < 4; nt++) {
                    const uint32_t b0 = b[nt >> 1][(nt & 1) * 2];
                    const uint32_t b1 = b[nt >> 1][(nt & 1) * 2 + 1];
                    MMA16816(acc[mt][nt], ahi[mt], b0, b1);
                }
        }
        __syncthreads();
        if (kb + 2 < G2_KITER)
            g2_prefetch(kb + 2, stage, bm, t);
        asm volatile("cp.async.commit_group;");
    }

    // epilogue: h2 store + fused layer-2 scores
    const int r_base = bm + mw + (lane >> 2);
    const int c_base = nw + (lane & 3) * 2;
#pragma unroll
    for (int mt = 0; mt < 2; mt++) {
#pragma unroll
        for (int nt = 0; nt < 4; nt++) {
            int r0 = r_base + mt * 16;
            int cc = c_base + nt * 8;
            if (cc < NCLASS) {
                if (r0 < N_NODES)
                    *(float2*)(g_h2 + (size_t)r0 * NCLASS + cc) = make_float2(acc[mt][nt][0], acc[mt][nt][1]);
                if (r0 + 8 < N_NODES)
                    *(float2*)(g_h2 + (size_t)(r0 + 8) * NCLASS + cc) = make_float2(acc[mt][nt][2], acc[mt][nt][3]);
            }
        }
    }
#pragma unroll
    for (int mt = 0; mt < 2; mt++) {
        float s0 = 0.f, d0 = 0.f, s1 = 0.f, d1 = 0.f;
#pragma unroll
        for (int nt = 0; nt < 4; nt++) {
#pragma unroll
            for (int je = 0; je < 2; je++) {
                int cc = c_base + nt * 8 + je;
                float a_s = (cc < NCLASS) ? a2[cc] : 0.f;
                float a_d = (cc < NCLASS) ? a2[NCLASS + cc] : 0.f;
                s0 += acc[mt][nt][je] * a_s;
                d0 += acc[mt][nt][je] * a_d;
                s1 += acc[mt][nt][2 + je] * a_s;
                d1 += acc[mt][nt][2 + je] * a_d;
            }
        }
        s0 += __shfl_xor_sync(0xffffffffu, s0, 1); s0 += __shfl_xor_sync(0xffffffffu, s0, 2);
        d0 += __shfl_xor_sync(0xffffffffu, d0, 1); d0 += __shfl_xor_sync(0xffffffffu, d0, 2);
        s1 += __shfl_xor_sync(0xffffffffu, s1, 1); s1 += __shfl_xor_sync(0xffffffffu, s1, 2);
        d1 += __shfl_xor_sync(0xffffffffu, d1, 1); d1 += __shfl_xor_sync(0xffffffffu, d1, 2);
        if ((lane & 3) == 0) {
            int r0 = r_base + mt * 16;
            if (r0 < N_NODES) {
                atomicAdd(&g_s2s[r0], s0);
                atomicAdd(&g_s2d[r0], d0);
            }
            if (r0 + 8 < N_NODES) {
                atomicAdd(&g_s2s[r0 + 8], s1);
                atomicAdd(&g_s2d[r0 + 8], d1);
            }
        }
    }
}

__device__ __forceinline__ float lrelu(float x) { return x > 0.f ? x : NEG * x; }

// ---------------- layer-1 softmax-aggregate (fp16 gather, split bf16 out) ---
__global__ __launch_bounds__(256) void k_agg1(const float* __restrict__ b1) {
    int n    = (blockIdx.x * blockDim.x + threadIdx.x) >> 5;
    int lane = threadIdx.x & 31;
    if (n >= N_NODES) return;
    const int beg = g_off[n], end = g_off[n + 1];

    const int h  = lane & 7;
    const int es = lane >> 3;
    const float sdh = g_s1d[n * NHEAD + h];

    float m = -1e30f;
    for (int i = beg + es; i < end; i += 4) {
        int s = g_csr_src[i];
        float e = lrelu(g_s1s[s * NHEAD + h] + sdh);
        m = fmaxf(m, e);
    }
    m = fmaxf(m, __shfl_xor_sync(0xffffffffu, m, 8));
    m = fmaxf(m, __shfl_xor_sync(0xffffffffu, m, 16));

    float den = 0.f;
    for (int i = beg + es; i < end; i += 4) {
        int s = g_csr_src[i];
        float e = lrelu(g_s1s[s * NHEAD + h] + sdh);
        den += __expf(e - m);
    }
    den += __shfl_xor_sync(0xffffffffu, den, 8);
    den += __shfl_xor_sync(0xffffffffu, den, 16);
    den = fmaxf(den, 1e-16f);

    float acc[16];
#pragma unroll
    for (int j = 0; j < 16; j++) acc[j] = 0.f;
    const int hl = lane >> 2;

    for (int i = beg; i < end; i++) {
        int s = g_csr_src[i];
        float alpha = 0.f;
        if (lane < 8) {
            float e = lrelu(g_s1s[s * NHEAD + lane] + sdh);
            alpha = __expf(e - m) / den;
        }
        alpha = __shfl_sync(0xffffffffu, alpha, hl);
        const uint4* hp = (const uint4*)(g_h1h + (size_t)s * F1 + lane * 16);
        uint4 q0 = hp[0];
        uint4 q1 = hp[1];
        float2 f;
        f = __half22float2(*(__half2*)&q0.x); acc[0] += alpha * f.x; acc[1] += alpha * f.y;
        f = __half22float2(*(__half2*)&q0.y); acc[2] += alpha * f.x; acc[3] += alpha * f.y;
        f = __half22float2(*(__half2*)&q0.z); acc[4] += alpha * f.x; acc[5] += alpha * f.y;
        f = __half22float2(*(__half2*)&q0.w); acc[6] += alpha * f.x; acc[7] += alpha * f.y;
        f = __half22float2(*(__half2*)&q1.x); acc[8] += alpha * f.x; acc[9] += alpha * f.y;
        f = __half22float2(*(__half2*)&q1.y); acc[10] += alpha * f.x; acc[11] += alpha * f.y;
        f = __half22float2(*(__half2*)&q1.z); acc[12] += alpha * f.x; acc[13] += alpha * f.y;
        f = __half22float2(*(__half2*)&q1.w); acc[14] += alpha * f.x; acc[15] += alpha * f.y;
    }

    const float4* bp = (const float4*)(b1 + lane * 16);
#pragma unroll
    for (int j = 0; j < 4; j++) {
        float4 b = bp[j];
        float v[4];
        v[0] = acc[j * 4 + 0] + b.x;
        v[1] = acc[j * 4 + 1] + b.y;
        v[2] = acc[j * 4 + 2] + b.z;
        v[3] = acc[j * 4 + 3] + b.w;
        __nv_bfloat16 hi[4], lo[4];
#pragma unroll
        for (int q = 0; q < 4; q++) {
            float e = v[q] > 0.f ? v[q] : expm1f(v[q]);
            hi[q] = __float2bfloat16(e);
            lo[q] = __float2bfloat16(e - __bfloat162float(hi[q]));
        }
        *(uint2*)(g_zhi + (size_t)n * F1 + lane * 16 + j * 4) = *(uint2*)hi;
        *(uint2*)(g_zlo + (size_t)n * F1 + lane * 16 + j * 4) = *(uint2*)lo;
    }
}

// ---------------- layer-2 aggregate + bias + log_softmax --------------------
__global__ __launch_bounds__(256) void k_agg2(const float* __restrict__ b2,
                                              float* __restrict__ out) {
    int n    = (blockIdx.x * blockDim.x + threadIdx.x) >> 5;
    int lane = threadIdx.x & 31;
    if (n >= N_NODES) return;
    const int beg = g_off[n], end = g_off[n + 1];
    const float sdn = g_s2d[n];

    float m = -1e30f;
    for (int i = beg + lane; i < end; i += 32) {
        int s = g_csr_src[i];
        m = fmaxf(m, lrelu(g_s2s[s] + sdn));
    }
#pragma unroll
    for (int off = 16; off > 0; off >>= 1)
        m = fmaxf(m, __shfl_xor_sync(0xffffffffu, m, off));

    float den = 0.f;
    for (int i = beg + lane; i < end; i += 32) {
        int s = g_csr_src[i];
        den += __expf(lrelu(g_s2s[s] + sdn) - m);
    }
#pragma unroll
    for (int off = 16; off > 0; off >>= 1)
        den += __shfl_xor_sync(0xffffffffu, den, off);
    den = fmaxf(den, 1e-16f);

    float acc0 = 0.f, acc1 = 0.f;
    for (int i = beg; i < end; i++) {
        int s = g_csr_src[i];
        float e = lrelu(g_s2s[s] + sdn);
        float alpha = __expf(e - m) / den;
        acc0 += alpha * g_h2[(size_t)s * NCLASS + lane];
        if (lane < 8) acc1 += alpha * g_h2[(size_t)s * NCLASS + 32 + lane];
    }

    float v0 = acc0 + b2[lane];
    float v1 = (lane < 8) ? (acc1 + b2[32 + lane]) : -1e30f;

    float mx = fmaxf(v0, v1);
#pragma unroll
    for (int off = 16; off > 0; off >>= 1)
        mx = fmaxf(mx, __shfl_xor_sync(0xffffffffu, mx, off));
    float se = __expf(v0 - mx) + ((lane < 8) ? __expf(v1 - mx) : 0.f);
#pragma unroll
    for (int off = 16; off > 0; off >>= 1)
        se += __shfl_xor_sync(0xffffffffu, se, off);
    float ls = logf(se);

    out[(size_t)n * NCLASS + lane] = v0 - mx - ls;
    if (lane < 8) out[(size_t)n * NCLASS + 32 + lane] = v1 - mx - ls;
}

// ---------------- launch -----------------------------------------------------
extern "C" void kernel_launch(void* const* d_in, const int* in_sizes, int n_in,
                              void* d_out, int out_size) {
    const float* x  = (const float*)d_in[0];
    const int*   el = (const int*)d_in[1];
    const float* W1 = (const float*)d_in[2];
    const float* a1 = (const float*)d_in[3];
    const float* b1 = (const float*)d_in[4];
    const float* W2 = (const float*)d_in[5];
    const float* a2 = (const float*)d_in[6];
    const float* b2 = (const float*)d_in[7];
    float* out = (float*)d_out;

    const int* src = el;
    const int* dst = el + N_EDGES;

    static cudaStream_t s2 = nullptr;
    static cudaEvent_t ev_fork = nullptr, ev_join = nullptr;
    if (!s2) {
        cudaStreamCreateWithFlags(&s2, cudaStreamNonBlocking);
        cudaEventCreateWithFlags(&ev_fork, cudaEventDisableTiming);
        cudaEventCreateWithFlags(&ev_join, cudaEventDisableTiming);
        cudaFuncSetAttribute(k_gemm1_mma, cudaFuncAttributeMaxDynamicSharedMemorySize, G1_SMEM);
        cudaFuncSetAttribute(k_gemm2_mma, cudaFuncAttributeMaxDynamicSharedMemorySize, G2_SMEM);
    }

    const int TB = 256;
    const int NBLK = (N_NODES + 1023) / 1024;

    // fork FIRST: CSR build is independent of the GEMM path and runs alongside it
    cudaEventRecord(ev_fork, 0);
    cudaStreamWaitEvent(s2, ev_fork, 0);

    // main stream: convert + zero + gemm1 (gemm1 = submission index 3 for ncu)
    k_split_x<<<(N_NODES * NFEAT / 8 + TB - 1) / TB, TB>>>(x);                    // 0
    k_split_w<<<(F1 * NFEAT + TB - 1) / TB, TB>>>(W1);                            // 1
    k_zero_scores<<<(N_NODES * NHEAD + TB - 1) / TB, TB>>>();                     // 2
    k_gemm1_mma<<<dim3(F1 / G1_BN, (N_NODES + G1_BM - 1) / G1_BM), 256, G1_SMEM>>>(a1); // 3

    // side stream: CSR build + W2 split (runs concurrently with the above)
    k_zero_deg<<<(N_NODES + TB - 1) / TB, TB, 0, s2>>>();
    k_count<<<(N_EDGES + TB - 1) / TB, TB, 0, s2>>>(dst);
    k_scan_blk<<<NBLK, 256, 0, s2>>>();
    k_scan_top<<<1, 32, 0, s2>>>();
    k_scan_add<<<(N_NODES + TB - 1) / TB, TB, 0, s2>>>();
    k_fill<<<(N_EDGES + TB - 1) / TB, TB, 0, s2>>>(src, dst);
    k_split_w2<<<(N2PAD * F1 + TB - 1) / TB, TB, 0, s2>>>(W2);
    cudaEventRecord(ev_join, s2);

    // main stream rejoins, then the dependent chain
    cudaStreamWaitEvent(0, ev_join, 0);
    k_agg1<<<(N_NODES + 7) / 8, 256>>>(b1);
    k_gemm2_mma<<<(N_NODES + G2_BM - 1) / G2_BM, 256, G2_SMEM>>>(a2);
    k_agg2<<<(N_NODES + 7) / 8, 256>>>(b2, out);
}

// round 15
// speedup vs baseline: 1.5499x; 1.0545x over previous
#include <cuda_runtime.h>
#include <cuda_bf16.h>
#include <cuda_fp16.h>
#include <cstdint>

#define N_NODES 50000
#define N_EDGES 800000
#define NFEAT   512
#define NHID    64
#define NHEAD   8
#define F1      512      // NHEAD*NHID
#define NCLASS  40
#define N2PAD   64
#define NEG     0.2f

// ---------------- scratch ---------------------------------------------------
__device__ __half g_h1h[(size_t)N_NODES * F1];   // fp16 gather copy of h1
__device__ float g_h2[(size_t)N_NODES * NCLASS];
__device__ float g_s1s[N_NODES * NHEAD];
__device__ float g_s1d[N_NODES * NHEAD];
__device__ float g_s2s[N_NODES];
__device__ float g_s2d[N_NODES];
__device__ int   g_deg[N_NODES];
__device__ int   g_off[N_NODES + 1];
__device__ int   g_cur[N_NODES];
__device__ int   g_csr_src[N_EDGES];
__device__ int   g_bsum[64];
__device__ int   g_bpre[64];
// fp16 operands
__device__ __half g_xh [(size_t)N_NODES * NFEAT];
__device__ __half g_WTh[F1 * NFEAT];             // [n][k], n = h*64+c
__device__ __half g_zh [(size_t)N_NODES * F1];   // layer-2 input (fp16)
__device__ __half g_W2h[N2PAD * F1];             // [n][k], n padded to 64

__device__ __forceinline__ uint32_t smem_u32(const void* p) {
    uint32_t a;
    asm("{ .reg .u64 t; cvta.to.shared.u64 t, %1; cvt.u32.u64 %0, t; }" : "=r"(a) : "l"(p));
    return a;
}

#define LDSM_X4(r0, r1, r2, r3, addr) \
    asm volatile("ldmatrix.sync.aligned.m8n8.x4.shared.b16 {%0,%1,%2,%3}, [%4];" \
                 : "=r"(r0), "=r"(r1), "=r"(r2), "=r"(r3) : "r"(addr))
#define MMA16816H(acc, a, b0, b1) \
    asm volatile("mma.sync.aligned.m16n8k16.row.col.f32.f16.f16.f32 " \
                 "{%0,%1,%2,%3}, {%4,%5,%6,%7}, {%8,%9}, {%0,%1,%2,%3};" \
                 : "+f"((acc)[0]), "+f"((acc)[1]), "+f"((acc)[2]), "+f"((acc)[3]) \
                 : "r"((a)[0]), "r"((a)[1]), "r"((a)[2]), "r"((a)[3]), "r"(b0), "r"(b1))

// ---------------- CSR construction ------------------------------------------
__global__ void k_zero_deg() {
    int i = blockIdx.x * blockDim.x + threadIdx.x;
    if (i < N_NODES) g_deg[i] = 0;
}
__global__ void k_zero_scores() {
    int i = blockIdx.x * blockDim.x + threadIdx.x;
    if (i < N_NODES * NHEAD) {
        g_s1s[i] = 0.f;
        g_s1d[i] = 0.f;
    }
    if (i < N_NODES) {
        g_s2s[i] = 0.f;
        g_s2d[i] = 0.f;
    }
}
__global__ void k_count(const int* __restrict__ dst) {
    int e = blockIdx.x * blockDim.x + threadIdx.x;
    if (e < N_EDGES) atomicAdd(&g_deg[dst[e]], 1);
}
__global__ __launch_bounds__(256) void k_scan_blk() {
    __shared__ int wsum[8];
    const int blk = blockIdx.x, t = threadIdx.x;
    const int base = blk * 1024 + t * 4;
    int v[4], s = 0;
#pragma unroll
    for (int j = 0; j < 4; j++) {
        int i = base + j;
        v[j] = (i < N_NODES) ? g_deg[i] : 0;
        s += v[j];
    }
    const int lane = t & 31, w = t >> 5;
    int ps = s;
#pragma unroll
    for (int o = 1; o < 32; o <<= 1) {
        int y = __shfl_up_sync(0xffffffffu, ps, o);
        if (lane >= o) ps += y;
    }
    if (lane == 31) wsum[w] = ps;
    __syncthreads();
    if (w == 0) {
        int ws = (lane < 8) ? wsum[lane] : 0;
#pragma unroll
        for (int o = 1; o < 8; o <<= 1) {
            int y = __shfl_up_sync(0xffffffffu, ws, o);
            if (lane >= o) ws += y;
        }
        if (lane < 8) wsum[lane] = ws;
    }
    __syncthreads();
    int run = ps - s + (w > 0 ? wsum[w - 1] : 0);
#pragma unroll
    for (int j = 0; j < 4; j++) {
        int i = base + j;
        if (i < N_NODES) g_off[i] = run;
        run += v[j];
    }
    if (t == 255) g_bsum[blk] = wsum[7];
}
__global__ void k_scan_top() {
    const int lane = threadIdx.x;
    const int nblk = (N_NODES + 1023) / 1024;
    int a = (lane < nblk) ? g_bsum[lane] : 0;
    int b = (lane + 32 < nblk) ? g_bsum[lane + 32] : 0;
    int pa = a;
#pragma unroll
    for (int o = 1; o < 32; o <<= 1) {
        int y = __shfl_up_sync(0xffffffffu, pa, o);
        if (lane >= o) pa += y;
    }
    int tot0 = __shfl_sync(0xffffffffu, pa, 31);
    int pb = b;
#pragma unroll
    for (int o = 1; o < 32; o <<= 1) {
        int y = __shfl_up_sync(0xffffffffu, pb, o);
        if (lane >= o) pb += y;
    }
    if (lane < nblk) g_bpre[lane] = pa - a;
    if (lane + 32 < nblk) g_bpre[lane + 32] = tot0 + pb - b;
}
__global__ void k_scan_add() {
    int i = blockIdx.x * blockDim.x + threadIdx.x;
    if (i < N_NODES) {
        int o = g_off[i] + g_bpre[i >> 10];
        g_off[i] = o;
        g_cur[i] = o;
    }
    if (i == 0) g_off[N_NODES] = N_EDGES;
}
__global__ void k_fill(const int* __restrict__ src, const int* __restrict__ dst) {
    int e = blockIdx.x * blockDim.x + threadIdx.x;
    if (e < N_EDGES) {
        int d = dst[e];
        int p = atomicAdd(&g_cur[d], 1);
        g_csr_src[p] = src[e];
    }
}

// ---------------- operand conversion -----------------------------------------
__global__ void k_split_x(const float* __restrict__ x) {
    int i = blockIdx.x * blockDim.x + threadIdx.x;
    const int total = N_NODES * NFEAT / 8;
    if (i >= total) return;
    const float4* p = (const float4*)x + (size_t)i * 2;
    float4 v0 = p[0], v1 = p[1];
    __half h[8];
    h[0] = __float2half(v0.x); h[1] = __float2half(v0.y);
    h[2] = __float2half(v0.z); h[3] = __float2half(v0.w);
    h[4] = __float2half(v1.x); h[5] = __float2half(v1.y);
    h[6] = __float2half(v1.z); h[7] = __float2half(v1.w);
    *(uint4*)(g_xh + (size_t)i * 8) = *(uint4*)h;
}
__global__ void k_split_w(const float* __restrict__ W1) {
    int idx = blockIdx.x * blockDim.x + threadIdx.x;
    if (idx >= F1 * NFEAT) return;
    int n = idx >> 9, k = idx & 511;
    int h = n >> 6, c = n & 63;
    g_WTh[(size_t)n * NFEAT + k] = __float2half(W1[((size_t)h * NFEAT + k) * NHID + c]);
}
__global__ void k_split_w2(const float* __restrict__ W2) {
    int idx = blockIdx.x * blockDim.x + threadIdx.x;
    if (idx >= N2PAD * F1) return;
    int n = idx >> 9, k = idx & 511;
    float w = (n < NCLASS) ? W2[(size_t)k * NCLASS + n] : 0.f;
    g_W2h[(size_t)n * F1 + k] = __float2half(w);
}

// ---------------- GEMM1 (pure fp16 HMMA + fused scores) ----------------------
#define G1_BM     128
#define G1_BN     128
#define G1_KITER  16                 // 512 / 32
#define G1_ROWB   80
#define G1_REG    10240
#define G1_STAGE  (2 * G1_REG)       // A | B = 20480
#define G1_NSTG   3
#define G1_SMEM   (G1_NSTG * G1_STAGE)   // 61440

__device__ __forceinline__ void g1_prefetch(int kb, uint32_t stage, int bm, int bn, int t) {
    const int k_in = kb * 32;
#pragma unroll
    for (int i = 0; i < 4; i++) {
        int q = t + i * 256;
        int region = q >> 9;          // 0:A 1:B
        int idx = q & 511;
        int row = idx >> 2, c = idx & 3;
        uint32_t dst = stage + region * G1_REG + row * G1_ROWB + c * 16;
        if (region == 0) {
            int grow = bm + row;
            int ok = grow < N_NODES;
            if (!ok) grow = 0;
            const void* srcp = g_xh + (size_t)grow * NFEAT + k_in + c * 8;
            int sz = ok ? 16 : 0;
            asm volatile("cp.async.cg.shared.global [%0], [%1], 16, %2;"
                         :: "r"(dst), "l"(srcp), "r"(sz));
        } else {
            const void* srcp = g_WTh + (size_t)(bn + row) * NFEAT + k_in + c * 8;
            asm volatile("cp.async.cg.shared.global [%0], [%1], 16;"
                         :: "r"(dst), "l"(srcp));
        }
    }
}

__global__ __launch_bounds__(256, 2) void k_gemm1_mma(const float* __restrict__ a1) {
    extern __shared__ char dyn[];
    const uint32_t sbase = smem_u32(dyn);
    const int t    = threadIdx.x;
    const int wid  = t >> 5;
    const int lane = t & 31;
    const int bm   = blockIdx.y * G1_BM;
    const int bn   = blockIdx.x * G1_BN;
    const int mw   = (wid >> 2) * 64;
    const int nw   = (wid & 3) * 32;

    float acc[4][4][4];
#pragma unroll
    for (int mt = 0; mt < 4; mt++)
#pragma unroll
        for (int nt = 0; nt < 4; nt++)
#pragma unroll
            for (int j = 0; j < 4; j++) acc[mt][nt][j] = 0.f;

    g1_prefetch(0, sbase, bm, bn, t);
    asm volatile("cp.async.commit_group;");
    g1_prefetch(1, sbase + G1_STAGE, bm, bn, t);
    asm volatile("cp.async.commit_group;");
    g1_prefetch(2, sbase + 2 * G1_STAGE, bm, bn, t);
    asm volatile("cp.async.commit_group;");

    const uint32_t a_off = (mw + (lane & 15)) * G1_ROWB + ((lane >> 4) * 16);
    const uint32_t b_off = G1_REG + (nw + (lane & 7) + ((lane >> 4) << 3)) * G1_ROWB + (((lane >> 3) & 1) * 16);

    int st = 0;
    for (int kb = 0; kb < G1_KITER; kb++) {
        asm volatile("cp.async.wait_group 2;");
        __syncthreads();
        const uint32_t stage = sbase + st * G1_STAGE;

#pragma unroll
        for (int ks = 0; ks < 2; ks++) {
            uint32_t a[4][4];
#pragma unroll
            for (int mt = 0; mt < 4; mt++) {
                uint32_t ad = stage + a_off + mt * (16 * G1_ROWB) + ks * 32;
                LDSM_X4(a[mt][0], a[mt][1], a[mt][2], a[mt][3], ad);
            }
            uint32_t b[2][4];
#pragma unroll
            for (int np = 0; np < 2; np++) {
                uint32_t bd = stage + b_off + np * (16 * G1_ROWB) + ks * 32;
                LDSM_X4(b[np][0], b[np][1], b[np][2], b[np][3], bd);
            }
#pragma unroll
            for (int mt = 0; mt < 4; mt++)
#pragma unroll
                for (int nt = 0; nt < 4; nt++) {
                    const uint32_t b0 = b[nt >> 1][(nt & 1) * 2];
                    const uint32_t b1 = b[nt >> 1][(nt & 1) * 2 + 1];
                    MMA16816H(acc[mt][nt], a[mt], b0, b1);
                }
        }
        __syncthreads();
        if (kb + G1_NSTG < G1_KITER)
            g1_prefetch(kb + G1_NSTG, stage, bm, bn, t);
        asm volatile("cp.async.commit_group;");
        st = (st == G1_NSTG - 1) ? 0 : st + 1;
    }

    // epilogue: fp16 h1h + fused layer-1 attention scores
    const int r_base = bm + mw + (lane >> 2);
    const int hw = (bn + nw) >> 6;
    const int co0 = ((bn + nw) & 63) + (lane & 3) * 2;
#pragma unroll
    for (int mt = 0; mt < 4; mt++) {
#pragma unroll
        for (int nt = 0; nt < 4; nt++) {
            int r0 = r_base + mt * 16;
            int cc = bn + nw + (lane & 3) * 2 + nt * 8;
            if (r0 < N_NODES)
                *(__half2*)(g_h1h + (size_t)r0 * F1 + cc) = __floats2half2_rn(acc[mt][nt][0], acc[mt][nt][1]);
            if (r0 + 8 < N_NODES)
                *(__half2*)(g_h1h + (size_t)(r0 + 8) * F1 + cc) = __floats2half2_rn(acc[mt][nt][2], acc[mt][nt][3]);
        }
        float s0 = 0.f, d0 = 0.f, s1 = 0.f, d1 = 0.f;
#pragma unroll
        for (int nt = 0; nt < 4; nt++) {
#pragma unroll
            for (int je = 0; je < 2; je++) {
                int co = co0 + nt * 8 + je;
                float a_s = a1[hw * 128 + co];
                float a_d = a1[hw * 128 + 64 + co];
                s0 += acc[mt][nt][je] * a_s;
                d0 += acc[mt][nt][je] * a_d;
                s1 += acc[mt][nt][2 + je] * a_s;
                d1 += acc[mt][nt][2 + je] * a_d;
            }
        }
        s0 += __shfl_xor_sync(0xffffffffu, s0, 1); s0 += __shfl_xor_sync(0xffffffffu, s0, 2);
        d0 += __shfl_xor_sync(0xffffffffu, d0, 1); d0 += __shfl_xor_sync(0xffffffffu, d0, 2);
        s1 += __shfl_xor_sync(0xffffffffu, s1, 1); s1 += __shfl_xor_sync(0xffffffffu, s1, 2);
        d1 += __shfl_xor_sync(0xffffffffu, d1, 1); d1 += __shfl_xor_sync(0xffffffffu, d1, 2);
        if ((lane & 3) == 0) {
            int r0 = r_base + mt * 16;
            if (r0 < N_NODES) {
                atomicAdd(&g_s1s[r0 * NHEAD + hw], s0);
                atomicAdd(&g_s1d[r0 * NHEAD + hw], d0);
            }
            if (r0 + 8 < N_NODES) {
                atomicAdd(&g_s1s[(r0 + 8) * NHEAD + hw], s1);
                atomicAdd(&g_s1d[(r0 + 8) * NHEAD + hw], d1);
            }
        }
    }
}

// ---------------- GEMM2 (pure fp16 HMMA + fused layer-2 scores) --------------
#define G2_BM     128
#define G2_KITER  16
#define G2_AREG   10240
#define G2_BREG   5120
#define G2_STAGE  (G2_AREG + G2_BREG)    // 15360
#define G2_NSTG   3
#define G2_SMEM   (G2_NSTG * G2_STAGE)   // 46080

__device__ __forceinline__ void g2_prefetch(int kb, uint32_t stage, int bm, int t) {
    const int k_in = kb * 32;
#pragma unroll
    for (int i = 0; i < 3; i++) {
        int q = t + i * 256;
        if (q < 512) {                  // A: 128 rows x 4 chunks
            int row = q >> 2, c = q & 3;
            uint32_t dst = stage + row * G1_ROWB + c * 16;
            int grow = bm + row;
            int ok = grow < N_NODES;
            if (!ok) grow = 0;
            const void* srcp = g_zh + (size_t)grow * F1 + k_in + c * 8;
            int sz = ok ? 16 : 0;
            asm volatile("cp.async.cg.shared.global [%0], [%1], 16, %2;"
                         :: "r"(dst), "l"(srcp), "r"(sz));
        } else {                        // B: 64 rows x 4 chunks
            int qb = q - 512;
            int row = qb >> 2, c = qb & 3;
            uint32_t dst = stage + G2_AREG + row * G1_ROWB + c * 16;
            const void* srcp = g_W2h + (size_t)row * F1 + k_in + c * 8;
            asm volatile("cp.async.cg.shared.global [%0], [%1], 16;"
                         :: "r"(dst), "l"(srcp));
        }
    }
}

__global__ __launch_bounds__(256, 2) void k_gemm2_mma(const float* __restrict__ a2) {
    extern __shared__ char dyn[];
    const uint32_t sbase = smem_u32(dyn);
    const int t    = threadIdx.x;
    const int wid  = t >> 5;
    const int lane = t & 31;
    const int bm   = blockIdx.x * G2_BM;
    const int mw   = (wid >> 1) * 32;
    const int nw   = (wid & 1) * 32;

    float acc[2][4][4];
#pragma unroll
    for (int mt = 0; mt < 2; mt++)
#pragma unroll
        for (int nt = 0; nt < 4; nt++)
#pragma unroll
            for (int j = 0; j < 4; j++) acc[mt][nt][j] = 0.f;

    g2_prefetch(0, sbase, bm, t);
    asm volatile("cp.async.commit_group;");
    g2_prefetch(1, sbase + G2_STAGE, bm, t);
    asm volatile("cp.async.commit_group;");
    g2_prefetch(2, sbase + 2 * G2_STAGE, bm, t);
    asm volatile("cp.async.commit_group;");

    const uint32_t a_off = (mw + (lane & 15)) * G1_ROWB + ((lane >> 4) * 16);
    const uint32_t b_off = G2_AREG + (nw + (lane & 7) + ((lane >> 4) << 3)) * G1_ROWB + (((lane >> 3) & 1) * 16);

    int st = 0;
    for (int kb = 0; kb < G2_KITER; kb++) {
        asm volatile("cp.async.wait_group 2;");
        __syncthreads();
        const uint32_t stage = sbase + st * G2_STAGE;

#pragma unroll
        for (int ks = 0; ks < 2; ks++) {
            uint32_t a[2][4];
#pragma unroll
            for (int mt = 0; mt < 2; mt++) {
                uint32_t ad = stage + a_off + mt * (16 * G1_ROWB) + ks * 32;
                LDSM_X4(a[mt][0], a[mt][1], a[mt][2], a[mt][3], ad);
            }
            uint32_t b[2][4];
#pragma unroll
            for (int np = 0; np < 2; np++) {
                uint32_t bd = stage + b_off + np * (16 * G1_ROWB) + ks * 32;
                LDSM_X4(b[np][0], b[np][1], b[np][2], b[np][3], bd);
            }
#pragma unroll
            for (int mt = 0; mt < 2; mt++)
#pragma unroll
                for (int nt = 0; nt < 4; nt++) {
                    const uint32_t b0 = b[nt >> 1][(nt & 1) * 2];
                    const uint32_t b1 = b[nt >> 1][(nt & 1) * 2 + 1];
                    MMA16816H(acc[mt][nt], a[mt], b0, b1);
                }
        }
        __syncthreads();
        if (kb + G2_NSTG < G2_KITER)
            g2_prefetch(kb + G2_NSTG, stage, bm, t);
        asm volatile("cp.async.commit_group;");
        st = (st == G2_NSTG - 1) ? 0 : st + 1;
    }

    // epilogue: h2 store + fused layer-2 scores
    const int r_base = bm + mw + (lane >> 2);
    const int c_base = nw + (lane & 3) * 2;
#pragma unroll
    for (int mt = 0; mt < 2; mt++) {
#pragma unroll
        for (int nt = 0; nt < 4; nt++) {
            int r0 = r_base + mt * 16;
            int cc = c_base + nt * 8;
            if (cc < NCLASS) {
                if (r0 < N_NODES)
                    *(float2*)(g_h2 + (size_t)r0 * NCLASS + cc) = make_float2(acc[mt][nt][0], acc[mt][nt][1]);
                if (r0 + 8 < N_NODES)
                    *(float2*)(g_h2 + (size_t)(r0 + 8) * NCLASS + cc) = make_float2(acc[mt][nt][2], acc[mt][nt][3]);
            }
        }
    }
#pragma unroll
    for (int mt = 0; mt < 2; mt++) {
        float s0 = 0.f, d0 = 0.f, s1 = 0.f, d1 = 0.f;
#pragma unroll
        for (int nt = 0; nt < 4; nt++) {
#pragma unroll
            for (int je = 0; je < 2; je++) {
                int cc = c_base + nt * 8 + je;
                float a_s = (cc < NCLASS) ? a2[cc] : 0.f;
                float a_d = (cc < NCLASS) ? a2[NCLASS + cc] : 0.f;
                s0 += acc[mt][nt][je] * a_s;
                d0 += acc[mt][nt][je] * a_d;
                s1 += acc[mt][nt][2 + je] * a_s;
                d1 += acc[mt][nt][2 + je] * a_d;
            }
        }
        s0 += __shfl_xor_sync(0xffffffffu, s0, 1); s0 += __shfl_xor_sync(0xffffffffu, s0, 2);
        d0 += __shfl_xor_sync(0xffffffffu, d0, 1); d0 += __shfl_xor_sync(0xffffffffu, d0, 2);
        s1 += __shfl_xor_sync(0xffffffffu, s1, 1); s1 += __shfl_xor_sync(0xffffffffu, s1, 2);
        d1 += __shfl_xor_sync(0xffffffffu, d1, 1); d1 += __shfl_xor_sync(0xffffffffu, d1, 2);
        if ((lane & 3) == 0) {
            int r0 = r_base + mt * 16;
            if (r0 < N_NODES) {
                atomicAdd(&g_s2s[r0], s0);
                atomicAdd(&g_s2d[r0], d0);
            }
            if (r0 + 8 < N_NODES) {
                atomicAdd(&g_s2s[r0 + 8], s1);
                atomicAdd(&g_s2d[r0 + 8], d1);
            }
        }
    }
}

__device__ __forceinline__ float lrelu(float x) { return x > 0.f ? x : NEG * x; }

// ---------------- layer-1 softmax-aggregate (fp16 gather, fp16 z out) -------
__global__ __launch_bounds__(256) void k_agg1(const float* __restrict__ b1) {
    int n    = (blockIdx.x * blockDim.x + threadIdx.x) >> 5;
    int lane = threadIdx.x & 31;
    if (n >= N_NODES) return;
    const int beg = g_off[n], end = g_off[n + 1];

    const int h  = lane & 7;
    const int es = lane >> 3;
    const float sdh = g_s1d[n * NHEAD + h];

    float m = -1e30f;
    for (int i = beg + es; i < end; i += 4) {
        int s = g_csr_src[i];
        float e = lrelu(g_s1s[s * NHEAD + h] + sdh);
        m = fmaxf(m, e);
    }
    m = fmaxf(m, __shfl_xor_sync(0xffffffffu, m, 8));
    m = fmaxf(m, __shfl_xor_sync(0xffffffffu, m, 16));

    float den = 0.f;
    for (int i = beg + es; i < end; i += 4) {
        int s = g_csr_src[i];
        float e = lrelu(g_s1s[s * NHEAD + h] + sdh);
        den += __expf(e - m);
    }
    den += __shfl_xor_sync(0xffffffffu, den, 8);
    den += __shfl_xor_sync(0xffffffffu, den, 16);
    den = fmaxf(den, 1e-16f);

    float acc[16];
#pragma unroll
    for (int j = 0; j < 16; j++) acc[j] = 0.f;
    const int hl = lane >> 2;

    for (int i = beg; i < end; i++) {
        int s = g_csr_src[i];
        float alpha = 0.f;
        if (lane < 8) {
            float e = lrelu(g_s1s[s * NHEAD + lane] + sdh);
            alpha = __expf(e - m) / den;
        }
        alpha = __shfl_sync(0xffffffffu, alpha, hl);
        const uint4* hp = (const uint4*)(g_h1h + (size_t)s * F1 + lane * 16);
        uint4 q0 = hp[0];
        uint4 q1 = hp[1];
        float2 f;
        f = __half22float2(*(__half2*)&q0.x); acc[0] += alpha * f.x; acc[1] += alpha * f.y;
        f = __half22float2(*(__half2*)&q0.y); acc[2] += alpha * f.x; acc[3] += alpha * f.y;
        f = __half22float2(*(__half2*)&q0.z); acc[4] += alpha * f.x; acc[5] += alpha * f.y;
        f = __half22float2(*(__half2*)&q0.w); acc[6] += alpha * f.x; acc[7] += alpha * f.y;
        f = __half22float2(*(__half2*)&q1.x); acc[8] += alpha * f.x; acc[9] += alpha * f.y;
        f = __half22float2(*(__half2*)&q1.y); acc[10] += alpha * f.x; acc[11] += alpha * f.y;
        f = __half22float2(*(__half2*)&q1.z); acc[12] += alpha * f.x; acc[13] += alpha * f.y;
        f = __half22float2(*(__half2*)&q1.w); acc[14] += alpha * f.x; acc[15] += alpha * f.y;
    }

    const float4* bp = (const float4*)(b1 + lane * 16);
    __half zh[16];
#pragma unroll
    for (int j = 0; j < 4; j++) {
        float4 b = bp[j];
        float v[4];
        v[0] = acc[j * 4 + 0] + b.x;
        v[1] = acc[j * 4 + 1] + b.y;
        v[2] = acc[j * 4 + 2] + b.z;
        v[3] = acc[j * 4 + 3] + b.w;
#pragma unroll
        for (int q = 0; q < 4; q++) {
            float e = v[q] > 0.f ? v[q] : expm1f(v[q]);
            zh[j * 4 + q] = __float2half(e);
        }
    }
    *(uint4*)(g_zh + (size_t)n * F1 + lane * 16)     = *(uint4*)(zh);
    *(uint4*)(g_zh + (size_t)n * F1 + lane * 16 + 8) = *(uint4*)(zh + 8);
}

// ---------------- layer-2 aggregate + bias + log_softmax --------------------
__global__ __launch_bounds__(256) void k_agg2(const float* __restrict__ b2,
                                              float* __restrict__ out) {
    int n    = (blockIdx.x * blockDim.x + threadIdx.x) >> 5;
    int lane = threadIdx.x & 31;
    if (n >= N_NODES) return;
    const int beg = g_off[n], end = g_off[n + 1];
    const float sdn = g_s2d[n];

    float m = -1e30f;
    for (int i = beg + lane; i < end; i += 32) {
        int s = g_csr_src[i];
        m = fmaxf(m, lrelu(g_s2s[s] + sdn));
    }
#pragma unroll
    for (int off = 16; off > 0; off >>= 1)
        m = fmaxf(m, __shfl_xor_sync(0xffffffffu, m, off));

    float den = 0.f;
    for (int i = beg + lane; i < end; i += 32) {
        int s = g_csr_src[i];
        den += __expf(lrelu(g_s2s[s] + sdn) - m);
    }
#pragma unroll
    for (int off = 16; off > 0; off >>= 1)
        den += __shfl_xor_sync(0xffffffffu, den, off);
    den = fmaxf(den, 1e-16f);

    float acc0 = 0.f, acc1 = 0.f;
    for (int i = beg; i < end; i++) {
        int s = g_csr_src[i];
        float e = lrelu(g_s2s[s] + sdn);
        float alpha = __expf(e - m) / den;
        acc0 += alpha * g_h2[(size_t)s * NCLASS + lane];
        if (lane < 8) acc1 += alpha * g_h2[(size_t)s * NCLASS + 32 + lane];
    }

    float v0 = acc0 + b2[lane];
    float v1 = (lane < 8) ? (acc1 + b2[32 + lane]) : -1e30f;

    float mx = fmaxf(v0, v1);
#pragma unroll
    for (int off = 16; off > 0; off >>= 1)
        mx = fmaxf(mx, __shfl_xor_sync(0xffffffffu, mx, off));
    float se = __expf(v0 - mx) + ((lane < 8) ? __expf(v1 - mx) : 0.f);
#pragma unroll
    for (int off = 16; off > 0; off >>= 1)
        se += __shfl_xor_sync(0xffffffffu, se, off);
    float ls = logf(se);

    out[(size_t)n * NCLASS + lane] = v0 - mx - ls;
    if (lane < 8) out[(size_t)n * NCLASS + 32 + lane] = v1 - mx - ls;
}

// ---------------- launch -----------------------------------------------------
extern "C" void kernel_launch(void* const* d_in, const int* in_sizes, int n_in,
                              void* d_out, int out_size) {
    const float* x  = (const float*)d_in[0];
    const int*   el = (const int*)d_in[1];
    const float* W1 = (const float*)d_in[2];
    const float* a1 = (const float*)d_in[3];
    const float* b1 = (const float*)d_in[4];
    const float* W2 = (const float*)d_in[5];
    const float* a2 = (const float*)d_in[6];
    const float* b2 = (const float*)d_in[7];
    float* out = (float*)d_out;

    const int* src = el;
    const int* dst = el + N_EDGES;

    static cudaStream_t s2 = nullptr;
    static cudaEvent_t ev_fork = nullptr, ev_join = nullptr;
    if (!s2) {
        cudaStreamCreateWithFlags(&s2, cudaStreamNonBlocking);
        cudaEventCreateWithFlags(&ev_fork, cudaEventDisableTiming);
        cudaEventCreateWithFlags(&ev_join, cudaEventDisableTiming);
        cudaFuncSetAttribute(k_gemm1_mma, cudaFuncAttributeMaxDynamicSharedMemorySize, G1_SMEM);
        cudaFuncSetAttribute(k_gemm2_mma, cudaFuncAttributeMaxDynamicSharedMemorySize, G2_SMEM);
    }

    const int TB = 256;
    const int NBLK = (N_NODES + 1023) / 1024;

    // fork FIRST: CSR build is independent of the GEMM path and runs alongside it
    cudaEventRecord(ev_fork, 0);
    cudaStreamWaitEvent(s2, ev_fork, 0);

    // main stream: convert + zero + gemm1 (gemm1 = submission index 3 for ncu)
    k_split_x<<<(N_NODES * NFEAT / 8 + TB - 1) / TB, TB>>>(x);                    // 0
    k_split_w<<<(F1 * NFEAT + TB - 1) / TB, TB>>>(W1);                            // 1
    k_zero_scores<<<(N_NODES * NHEAD + TB - 1) / TB, TB>>>();                     // 2
    k_gemm1_mma<<<dim3(F1 / G1_BN, (N_NODES + G1_BM - 1) / G1_BM), 256, G1_SMEM>>>(a1); // 3

    // side stream: CSR build + W2 split (runs concurrently with the above)
    k_zero_deg<<<(N_NODES + TB - 1) / TB, TB, 0, s2>>>();
    k_count<<<(N_EDGES + TB - 1) / TB, TB, 0, s2>>>(dst);
    k_scan_blk<<<NBLK, 256, 0, s2>>>();
    k_scan_top<<<1, 32, 0, s2>>>();
    k_scan_add<<<(N_NODES + TB - 1) / TB, TB, 0, s2>>>();
    k_fill<<<(N_EDGES + TB - 1) / TB, TB, 0, s2>>>(src, dst);
    k_split_w2<<<(N2PAD * F1 + TB - 1) / TB, TB, 0, s2>>>(W2);
    cudaEventRecord(ev_join, s2);

    // main stream rejoins, then the dependent chain
    cudaStreamWaitEvent(0, ev_join, 0);
    k_agg1<<<(N_NODES + 7) / 8, 256>>>(b1);
    k_gemm2_mma<<<(N_NODES + G2_BM - 1) / G2_BM, 256, G2_SMEM>>>(a2);
    k_agg2<<<(N_NODES + 7) / 8, 256>>>(b2, out);
}

// round 16
// speedup vs baseline: 1.6347x; 1.0547x over previous
#include <cuda_runtime.h>
#include <cuda_bf16.h>
#include <cuda_fp16.h>
#include <cstdint>

#define N_NODES 50000
#define N_EDGES 800000
#define NFEAT   512
#define NHID    64
#define NHEAD   8
#define F1      512      // NHEAD*NHID
#define NCLASS  40
#define N2PAD   64
#define NEG     0.2f

// ---------------- scratch ---------------------------------------------------
__device__ __half g_h1h[(size_t)N_NODES * F1];   // fp16 gather copy of h1
__device__ float g_h2[(size_t)N_NODES * NCLASS];
__device__ float g_s1s[N_NODES * NHEAD];
__device__ float g_s1d[N_NODES * NHEAD];
__device__ float g_s2s[N_NODES];
__device__ float g_s2d[N_NODES];
__device__ int   g_deg[N_NODES];
__device__ int   g_off[N_NODES + 1];
__device__ int   g_cur[N_NODES];
__device__ int   g_csr_src[N_EDGES];
__device__ int   g_bsum[64];
__device__ int   g_bpre[64];
// fp16 operands
__device__ __half g_xh [(size_t)N_NODES * NFEAT];
__device__ __half g_WTh[F1 * NFEAT];             // [n][k], n = h*64+c
__device__ __half g_zh [(size_t)N_NODES * F1];   // layer-2 input (fp16)
__device__ __half g_W2h[N2PAD * F1];             // [n][k], n padded to 64

__device__ __forceinline__ uint32_t smem_u32(const void* p) {
    uint32_t a;
    asm("{ .reg .u64 t; cvta.to.shared.u64 t, %1; cvt.u32.u64 %0, t; }" : "=r"(a) : "l"(p));
    return a;
}

#define LDSM_X4(r0, r1, r2, r3, addr) \
    asm volatile("ldmatrix.sync.aligned.m8n8.x4.shared.b16 {%0,%1,%2,%3}, [%4];" \
                 : "=r"(r0), "=r"(r1), "=r"(r2), "=r"(r3) : "r"(addr))
#define MMA16816H(acc, a, b0, b1) \
    asm volatile("mma.sync.aligned.m16n8k16.row.col.f32.f16.f16.f32 " \
                 "{%0,%1,%2,%3}, {%4,%5,%6,%7}, {%8,%9}, {%0,%1,%2,%3};" \
                 : "+f"((acc)[0]), "+f"((acc)[1]), "+f"((acc)[2]), "+f"((acc)[3]) \
                 : "r"((a)[0]), "r"((a)[1]), "r"((a)[2]), "r"((a)[3]), "r"(b0), "r"(b1))

// ---------------- CSR construction ------------------------------------------
__global__ void k_zero_deg() {
    int i = blockIdx.x * blockDim.x + threadIdx.x;
    if (i < N_NODES) g_deg[i] = 0;
}
__global__ void k_zero_scores() {
    int i = blockIdx.x * blockDim.x + threadIdx.x;
    if (i < N_NODES * NHEAD) {
        g_s1s[i] = 0.f;
        g_s1d[i] = 0.f;
    }
    if (i < N_NODES) {
        g_s2s[i] = 0.f;
        g_s2d[i] = 0.f;
    }
}
__global__ void k_count(const int* __restrict__ dst) {
    int e = blockIdx.x * blockDim.x + threadIdx.x;
    if (e < N_EDGES) atomicAdd(&g_deg[dst[e]], 1);
}
__global__ __launch_bounds__(256) void k_scan_blk() {
    __shared__ int wsum[8];
    const int blk = blockIdx.x, t = threadIdx.x;
    const int base = blk * 1024 + t * 4;
    int v[4], s = 0;
#pragma unroll
    for (int j = 0; j < 4; j++) {
        int i = base + j;
        v[j] = (i < N_NODES) ? g_deg[i] : 0;
        s += v[j];
    }
    const int lane = t & 31, w = t >> 5;
    int ps = s;
#pragma unroll
    for (int o = 1; o < 32; o <<= 1) {
        int y = __shfl_up_sync(0xffffffffu, ps, o);
        if (lane >= o) ps += y;
    }
    if (lane == 31) wsum[w] = ps;
    __syncthreads();
    if (w == 0) {
        int ws = (lane < 8) ? wsum[lane] : 0;
#pragma unroll
        for (int o = 1; o < 8; o <<= 1) {
            int y = __shfl_up_sync(0xffffffffu, ws, o);
            if (lane >= o) ws += y;
        }
        if (lane < 8) wsum[lane] = ws;
    }
    __syncthreads();
    int run = ps - s + (w > 0 ? wsum[w - 1] : 0);
#pragma unroll
    for (int j = 0; j < 4; j++) {
        int i = base + j;
        if (i < N_NODES) g_off[i] = run;
        run += v[j];
    }
    if (t == 255) g_bsum[blk] = wsum[7];
}
__global__ void k_scan_top() {
    const int lane = threadIdx.x;
    const int nblk = (N_NODES + 1023) / 1024;
    int a = (lane < nblk) ? g_bsum[lane] : 0;
    int b = (lane + 32 < nblk) ? g_bsum[lane + 32] : 0;
    int pa = a;
#pragma unroll
    for (int o = 1; o < 32; o <<= 1) {
        int y = __shfl_up_sync(0xffffffffu, pa, o);
        if (lane >= o) pa += y;
    }
    int tot0 = __shfl_sync(0xffffffffu, pa, 31);
    int pb = b;
#pragma unroll
    for (int o = 1; o < 32; o <<= 1) {
        int y = __shfl_up_sync(0xffffffffu, pb, o);
        if (lane >= o) pb += y;
    }
    if (lane < nblk) g_bpre[lane] = pa - a;
    if (lane + 32 < nblk) g_bpre[lane + 32] = tot0 + pb - b;
}
__global__ void k_scan_add() {
    int i = blockIdx.x * blockDim.x + threadIdx.x;
    if (i < N_NODES) {
        int o = g_off[i] + g_bpre[i >> 10];
        g_off[i] = o;
        g_cur[i] = o;
    }
    if (i == 0) g_off[N_NODES] = N_EDGES;
}
__global__ void k_fill(const int* __restrict__ src, const int* __restrict__ dst) {
    int e = blockIdx.x * blockDim.x + threadIdx.x;
    if (e < N_EDGES) {
        int d = dst[e];
        int p = atomicAdd(&g_cur[d], 1);
        g_csr_src[p] = src[e];
    }
}

// ---------------- operand conversion -----------------------------------------
__global__ void k_split_x(const float* __restrict__ x) {
    int i = blockIdx.x * blockDim.x + threadIdx.x;
    const int total = N_NODES * NFEAT / 8;
    if (i >= total) return;
    const float4* p = (const float4*)x + (size_t)i * 2;
    float4 v0 = p[0], v1 = p[1];
    __half h[8];
    h[0] = __float2half(v0.x); h[1] = __float2half(v0.y);
    h[2] = __float2half(v0.z); h[3] = __float2half(v0.w);
    h[4] = __float2half(v1.x); h[5] = __float2half(v1.y);
    h[6] = __float2half(v1.z); h[7] = __float2half(v1.w);
    *(uint4*)(g_xh + (size_t)i * 8) = *(uint4*)h;
}
__global__ void k_split_w(const float* __restrict__ W1) {
    int idx = blockIdx.x * blockDim.x + threadIdx.x;
    if (idx >= F1 * NFEAT) return;
    int n = idx >> 9, k = idx & 511;
    int h = n >> 6, c = n & 63;
    g_WTh[(size_t)n * NFEAT + k] = __float2half(W1[((size_t)h * NFEAT + k) * NHID + c]);
}
__global__ void k_split_w2(const float* __restrict__ W2) {
    int idx = blockIdx.x * blockDim.x + threadIdx.x;
    if (idx >= N2PAD * F1) return;
    int n = idx >> 9, k = idx & 511;
    float w = (n < NCLASS) ? W2[(size_t)k * NCLASS + n] : 0.f;
    g_W2h[(size_t)n * F1 + k] = __float2half(w);
}

// ---------------- GEMM1 (pure fp16 HMMA + fused scores) ----------------------
#define G1_BM     128
#define G1_BN     128
#define G1_KITER  16                 // 512 / 32
#define G1_ROWB   80
#define G1_REG    10240
#define G1_STAGE  (2 * G1_REG)       // A | B = 20480
#define G1_NSTG   3
#define G1_SMEM   (G1_NSTG * G1_STAGE)   // 61440

__device__ __forceinline__ void g1_prefetch(int kb, uint32_t stage, int bm, int bn, int t) {
    const int k_in = kb * 32;
#pragma unroll
    for (int i = 0; i < 4; i++) {
        int q = t + i * 256;
        int region = q >> 9;          // 0:A 1:B
        int idx = q & 511;
        int row = idx >> 2, c = idx & 3;
        uint32_t dst = stage + region * G1_REG + row * G1_ROWB + c * 16;
        if (region == 0) {
            int grow = bm + row;
            int ok = grow < N_NODES;
            if (!ok) grow = 0;
            const void* srcp = g_xh + (size_t)grow * NFEAT + k_in + c * 8;
            int sz = ok ? 16 : 0;
            asm volatile("cp.async.cg.shared.global [%0], [%1], 16, %2;"
                         :: "r"(dst), "l"(srcp), "r"(sz));
        } else {
            const void* srcp = g_WTh + (size_t)(bn + row) * NFEAT + k_in + c * 8;
            asm volatile("cp.async.cg.shared.global [%0], [%1], 16;"
                         :: "r"(dst), "l"(srcp));
        }
    }
}

__global__ __launch_bounds__(256, 2) void k_gemm1_mma(const float* __restrict__ a1) {
    extern __shared__ char dyn[];
    const uint32_t sbase = smem_u32(dyn);
    const int t    = threadIdx.x;
    const int wid  = t >> 5;
    const int lane = t & 31;
    const int bm   = blockIdx.y * G1_BM;
    const int bn   = blockIdx.x * G1_BN;
    const int mw   = (wid >> 2) * 64;
    const int nw   = (wid & 3) * 32;

    float acc[4][4][4];
#pragma unroll
    for (int mt = 0; mt < 4; mt++)
#pragma unroll
        for (int nt = 0; nt < 4; nt++)
#pragma unroll
            for (int j = 0; j < 4; j++) acc[mt][nt][j] = 0.f;

    g1_prefetch(0, sbase, bm, bn, t);
    asm volatile("cp.async.commit_group;");
    g1_prefetch(1, sbase + G1_STAGE, bm, bn, t);
    asm volatile("cp.async.commit_group;");
    g1_prefetch(2, sbase + 2 * G1_STAGE, bm, bn, t);
    asm volatile("cp.async.commit_group;");

    const uint32_t a_off = (mw + (lane & 15)) * G1_ROWB + ((lane >> 4) * 16);
    const uint32_t b_off = G1_REG + (nw + (lane & 7) + ((lane >> 4) << 3)) * G1_ROWB + (((lane >> 3) & 1) * 16);

    int st = 0;
    for (int kb = 0; kb < G1_KITER; kb++) {
        asm volatile("cp.async.wait_group 2;");
        __syncthreads();
        const uint32_t stage = sbase + st * G1_STAGE;

#pragma unroll
        for (int ks = 0; ks < 2; ks++) {
            uint32_t a[4][4];
#pragma unroll
            for (int mt = 0; mt < 4; mt++) {
                uint32_t ad = stage + a_off + mt * (16 * G1_ROWB) + ks * 32;
                LDSM_X4(a[mt][0], a[mt][1], a[mt][2], a[mt][3], ad);
            }
            uint32_t b[2][4];
#pragma unroll
            for (int np = 0; np < 2; np++) {
                uint32_t bd = stage + b_off + np * (16 * G1_ROWB) + ks * 32;
                LDSM_X4(b[np][0], b[np][1], b[np][2], b[np][3], bd);
            }
#pragma unroll
            for (int mt = 0; mt < 4; mt++)
#pragma unroll
                for (int nt = 0; nt < 4; nt++) {
                    const uint32_t b0 = b[nt >> 1][(nt & 1) * 2];
                    const uint32_t b1 = b[nt >> 1][(nt & 1) * 2 + 1];
                    MMA16816H(acc[mt][nt], a[mt], b0, b1);
                }
        }
        __syncthreads();
        if (kb + G1_NSTG < G1_KITER)
            g1_prefetch(kb + G1_NSTG, stage, bm, bn, t);
        asm volatile("cp.async.commit_group;");
        st = (st == G1_NSTG - 1) ? 0 : st + 1;
    }

    // epilogue: fp16 h1h + fused layer-1 attention scores
    const int r_base = bm + mw + (lane >> 2);
    const int hw = (bn + nw) >> 6;
    const int co0 = ((bn + nw) & 63) + (lane & 3) * 2;
#pragma unroll
    for (int mt = 0; mt < 4; mt++) {
#pragma unroll
        for (int nt = 0; nt < 4; nt++) {
            int r0 = r_base + mt * 16;
            int cc = bn + nw + (lane & 3) * 2 + nt * 8;
            if (r0 < N_NODES)
                *(__half2*)(g_h1h + (size_t)r0 * F1 + cc) = __floats2half2_rn(acc[mt][nt][0], acc[mt][nt][1]);
            if (r0 + 8 < N_NODES)
                *(__half2*)(g_h1h + (size_t)(r0 + 8) * F1 + cc) = __floats2half2_rn(acc[mt][nt][2], acc[mt][nt][3]);
        }
        float s0 = 0.f, d0 = 0.f, s1 = 0.f, d1 = 0.f;
#pragma unroll
        for (int nt = 0; nt < 4; nt++) {
#pragma unroll
            for (int je = 0; je < 2; je++) {
                int co = co0 + nt * 8 + je;
                float a_s = a1[hw * 128 + co];
                float a_d = a1[hw * 128 + 64 + co];
                s0 += acc[mt][nt][je] * a_s;
                d0 += acc[mt][nt][je] * a_d;
                s1 += acc[mt][nt][2 + je] * a_s;
                d1 += acc[mt][nt][2 + je] * a_d;
            }
        }
        s0 += __shfl_xor_sync(0xffffffffu, s0, 1); s0 += __shfl_xor_sync(0xffffffffu, s0, 2);
        d0 += __shfl_xor_sync(0xffffffffu, d0, 1); d0 += __shfl_xor_sync(0xffffffffu, d0, 2);
        s1 += __shfl_xor_sync(0xffffffffu, s1, 1); s1 += __shfl_xor_sync(0xffffffffu, s1, 2);
        d1 += __shfl_xor_sync(0xffffffffu, d1, 1); d1 += __shfl_xor_sync(0xffffffffu, d1, 2);
        if ((lane & 3) == 0) {
            int r0 = r_base + mt * 16;
            if (r0 < N_NODES) {
                atomicAdd(&g_s1s[r0 * NHEAD + hw], s0);
                atomicAdd(&g_s1d[r0 * NHEAD + hw], d0);
            }
            if (r0 + 8 < N_NODES) {
                atomicAdd(&g_s1s[(r0 + 8) * NHEAD + hw], s1);
                atomicAdd(&g_s1d[(r0 + 8) * NHEAD + hw], d1);
            }
        }
    }
}

// ---------------- GEMM2 (pure fp16 HMMA + fused layer-2 scores) --------------
#define G2_BM     128
#define G2_KITER  16
#define G2_AREG   10240
#define G2_BREG   5120
#define G2_STAGE  (G2_AREG + G2_BREG)    // 15360
#define G2_NSTG   3
#define G2_SMEM   (G2_NSTG * G2_STAGE)   // 46080

__device__ __forceinline__ void g2_prefetch(int kb, uint32_t stage, int bm, int t) {
    const int k_in = kb * 32;
#pragma unroll
    for (int i = 0; i < 3; i++) {
        int q = t + i * 256;
        if (q < 512) {                  // A: 128 rows x 4 chunks
            int row = q >> 2, c = q & 3;
            uint32_t dst = stage + row * G1_ROWB + c * 16;
            int grow = bm + row;
            int ok = grow < N_NODES;
            if (!ok) grow = 0;
            const void* srcp = g_zh + (size_t)grow * F1 + k_in + c * 8;
            int sz = ok ? 16 : 0;
            asm volatile("cp.async.cg.shared.global [%0], [%1], 16, %2;"
                         :: "r"(dst), "l"(srcp), "r"(sz));
        } else {                        // B: 64 rows x 4 chunks
            int qb = q - 512;
            int row = qb >> 2, c = qb & 3;
            uint32_t dst = stage + G2_AREG + row * G1_ROWB + c * 16;
            const void* srcp = g_W2h + (size_t)row * F1 + k_in + c * 8;
            asm volatile("cp.async.cg.shared.global [%0], [%1], 16;"
                         :: "r"(dst), "l"(srcp));
        }
    }
}

__global__ __launch_bounds__(256, 2) void k_gemm2_mma(const float* __restrict__ a2) {
    extern __shared__ char dyn[];
    const uint32_t sbase = smem_u32(dyn);
    const int t    = threadIdx.x;
    const int wid  = t >> 5;
    const int lane = t & 31;
    const int bm   = blockIdx.x * G2_BM;
    const int mw   = (wid >> 1) * 32;
    const int nw   = (wid & 1) * 32;

    float acc[2][4][4];
#pragma unroll
    for (int mt = 0; mt < 2; mt++)
#pragma unroll
        for (int nt = 0; nt < 4; nt++)
#pragma unroll
            for (int j = 0; j < 4; j++) acc[mt][nt][j] = 0.f;

    g2_prefetch(0, sbase, bm, t);
    asm volatile("cp.async.commit_group;");
    g2_prefetch(1, sbase + G2_STAGE, bm, t);
    asm volatile("cp.async.commit_group;");
    g2_prefetch(2, sbase + 2 * G2_STAGE, bm, t);
    asm volatile("cp.async.commit_group;");

    const uint32_t a_off = (mw + (lane & 15)) * G1_ROWB + ((lane >> 4) * 16);
    const uint32_t b_off = G2_AREG + (nw + (lane & 7) + ((lane >> 4) << 3)) * G1_ROWB + (((lane >> 3) & 1) * 16);

    int st = 0;
    for (int kb = 0; kb < G2_KITER; kb++) {
        asm volatile("cp.async.wait_group 2;");
        __syncthreads();
        const uint32_t stage = sbase + st * G2_STAGE;

#pragma unroll
        for (int ks = 0; ks < 2; ks++) {
            uint32_t a[2][4];
#pragma unroll
            for (int mt = 0; mt < 2; mt++) {
                uint32_t ad = stage + a_off + mt * (16 * G1_ROWB) + ks * 32;
                LDSM_X4(a[mt][0], a[mt][1], a[mt][2], a[mt][3], ad);
            }
            uint32_t b[2][4];
#pragma unroll
            for (int np = 0; np < 2; np++) {
                uint32_t bd = stage + b_off + np * (16 * G1_ROWB) + ks * 32;
                LDSM_X4(b[np][0], b[np][1], b[np][2], b[np][3], bd);
            }
#pragma unroll
            for (int mt = 0; mt < 2; mt++)
#pragma unroll
                for (int nt = 0; nt < 4; nt++) {
                    const uint32_t b0 = b[nt >> 1][(nt & 1) * 2];
                    const uint32_t b1 = b[nt >> 1][(nt & 1) * 2 + 1];
                    MMA16816H(acc[mt][nt], a[mt], b0, b1);
                }
        }
        __syncthreads();
        if (kb + G2_NSTG < G2_KITER)
            g2_prefetch(kb + G2_NSTG, stage, bm, t);
        asm volatile("cp.async.commit_group;");
        st = (st == G2_NSTG - 1) ? 0 : st + 1;
    }

    // epilogue: h2 store + fused layer-2 scores
    const int r_base = bm + mw + (lane >> 2);
    const int c_base = nw + (lane & 3) * 2;
#pragma unroll
    for (int mt = 0; mt < 2; mt++) {
#pragma unroll
        for (int nt = 0; nt < 4; nt++) {
            int r0 = r_base + mt * 16;
            int cc = c_base + nt * 8;
            if (cc < NCLASS) {
                if (r0 < N_NODES)
                    *(float2*)(g_h2 + (size_t)r0 * NCLASS + cc) = make_float2(acc[mt][nt][0], acc[mt][nt][1]);
                if (r0 + 8 < N_NODES)
                    *(float2*)(g_h2 + (size_t)(r0 + 8) * NCLASS + cc) = make_float2(acc[mt][nt][2], acc[mt][nt][3]);
            }
        }
    }
#pragma unroll
    for (int mt = 0; mt < 2; mt++) {
        float s0 = 0.f, d0 = 0.f, s1 = 0.f, d1 = 0.f;
#pragma unroll
        for (int nt = 0; nt < 4; nt++) {
#pragma unroll
            for (int je = 0; je < 2; je++) {
                int cc = c_base + nt * 8 + je;
                float a_s = (cc < NCLASS) ? a2[cc] : 0.f;
                float a_d = (cc < NCLASS) ? a2[NCLASS + cc] : 0.f;
                s0 += acc[mt][nt][je] * a_s;
                d0 += acc[mt][nt][je] * a_d;
                s1 += acc[mt][nt][2 + je] * a_s;
                d1 += acc[mt][nt][2 + je] * a_d;
            }
        }
        s0 += __shfl_xor_sync(0xffffffffu, s0, 1); s0 += __shfl_xor_sync(0xffffffffu, s0, 2);
        d0 += __shfl_xor_sync(0xffffffffu, d0, 1); d0 += __shfl_xor_sync(0xffffffffu, d0, 2);
        s1 += __shfl_xor_sync(0xffffffffu, s1, 1); s1 += __shfl_xor_sync(0xffffffffu, s1, 2);
        d1 += __shfl_xor_sync(0xffffffffu, d1, 1); d1 += __shfl_xor_sync(0xffffffffu, d1, 2);
        if ((lane & 3) == 0) {
            int r0 = r_base + mt * 16;
            if (r0 < N_NODES) {
                atomicAdd(&g_s2s[r0], s0);
                atomicAdd(&g_s2d[r0], d0);
            }
            if (r0 + 8 < N_NODES) {
                atomicAdd(&g_s2s[r0 + 8], s1);
                atomicAdd(&g_s2d[r0 + 8], d1);
            }
        }
    }
}

__device__ __forceinline__ float lrelu(float x) { return x > 0.f ? x : NEG * x; }

// ---------------- layer-1 softmax-aggregate (2-edge unrolled gather) --------
__device__ __forceinline__ void agg_edge(int s, float alpha, float* acc, int lane) {
    const uint4* hp = (const uint4*)(g_h1h + (size_t)s * F1 + lane * 16);
    uint4 q0 = hp[0];
    uint4 q1 = hp[1];
    float2 f;
    f = __half22float2(*(__half2*)&q0.x); acc[0] += alpha * f.x; acc[1] += alpha * f.y;
    f = __half22float2(*(__half2*)&q0.y); acc[2] += alpha * f.x; acc[3] += alpha * f.y;
    f = __half22float2(*(__half2*)&q0.z); acc[4] += alpha * f.x; acc[5] += alpha * f.y;
    f = __half22float2(*(__half2*)&q0.w); acc[6] += alpha * f.x; acc[7] += alpha * f.y;
    f = __half22float2(*(__half2*)&q1.x); acc[8] += alpha * f.x; acc[9] += alpha * f.y;
    f = __half22float2(*(__half2*)&q1.y); acc[10] += alpha * f.x; acc[11] += alpha * f.y;
    f = __half22float2(*(__half2*)&q1.z); acc[12] += alpha * f.x; acc[13] += alpha * f.y;
    f = __half22float2(*(__half2*)&q1.w); acc[14] += alpha * f.x; acc[15] += alpha * f.y;
}

__global__ __launch_bounds__(256) void k_agg1(const float* __restrict__ b1) {
    int n    = (blockIdx.x * blockDim.x + threadIdx.x) >> 5;
    int lane = threadIdx.x & 31;
    if (n >= N_NODES) return;
    const int beg = g_off[n], end = g_off[n + 1];

    const int h  = lane & 7;
    const int es = lane >> 3;
    const float sdh = g_s1d[n * NHEAD + h];

    float m = -1e30f;
    for (int i = beg + es; i < end; i += 4) {
        int s = g_csr_src[i];
        float e = lrelu(g_s1s[s * NHEAD + h] + sdh);
        m = fmaxf(m, e);
    }
    m = fmaxf(m, __shfl_xor_sync(0xffffffffu, m, 8));
    m = fmaxf(m, __shfl_xor_sync(0xffffffffu, m, 16));

    float den = 0.f;
    for (int i = beg + es; i < end; i += 4) {
        int s = g_csr_src[i];
        float e = lrelu(g_s1s[s * NHEAD + h] + sdh);
        den += __expf(e - m);
    }
    den += __shfl_xor_sync(0xffffffffu, den, 8);
    den += __shfl_xor_sync(0xffffffffu, den, 16);
    den = fmaxf(den, 1e-16f);
    const float rden = 1.f / den;

    float acc[16];
#pragma unroll
    for (int j = 0; j < 16; j++) acc[j] = 0.f;
    const int hl = lane >> 2;

    int i = beg;
    for (; i + 1 < end; i += 2) {
        int s0 = g_csr_src[i];
        int s1 = g_csr_src[i + 1];
        float al0 = 0.f, al1 = 0.f;
        if (lane < 8) {
            float e0 = lrelu(g_s1s[s0 * NHEAD + lane] + sdh);
            float e1 = lrelu(g_s1s[s1 * NHEAD + lane] + sdh);
            al0 = __expf(e0 - m) * rden;
            al1 = __expf(e1 - m) * rden;
        }
        al0 = __shfl_sync(0xffffffffu, al0, hl);
        al1 = __shfl_sync(0xffffffffu, al1, hl);
        // issue both edges' gathers before FMAs (compiler interleaves)
        agg_edge(s0, al0, acc, lane);
        agg_edge(s1, al1, acc, lane);
    }
    if (i < end) {
        int s0 = g_csr_src[i];
        float al0 = 0.f;
        if (lane < 8) {
            float e0 = lrelu(g_s1s[s0 * NHEAD + lane] + sdh);
            al0 = __expf(e0 - m) * rden;
        }
        al0 = __shfl_sync(0xffffffffu, al0, hl);
        agg_edge(s0, al0, acc, lane);
    }

    const float4* bp = (const float4*)(b1 + lane * 16);
    __half zh[16];
#pragma unroll
    for (int j = 0; j < 4; j++) {
        float4 b = bp[j];
        float v[4];
        v[0] = acc[j * 4 + 0] + b.x;
        v[1] = acc[j * 4 + 1] + b.y;
        v[2] = acc[j * 4 + 2] + b.z;
        v[3] = acc[j * 4 + 3] + b.w;
#pragma unroll
        for (int q = 0; q < 4; q++) {
            float e = v[q] > 0.f ? v[q] : expm1f(v[q]);
            zh[j * 4 + q] = __float2half(e);
        }
    }
    *(uint4*)(g_zh + (size_t)n * F1 + lane * 16)     = *(uint4*)(zh);
    *(uint4*)(g_zh + (size_t)n * F1 + lane * 16 + 8) = *(uint4*)(zh + 8);
}

// ---------------- layer-2 aggregate + bias + log_softmax --------------------
__global__ __launch_bounds__(256) void k_agg2(const float* __restrict__ b2,
                                              float* __restrict__ out) {
    int n    = (blockIdx.x * blockDim.x + threadIdx.x) >> 5;
    int lane = threadIdx.x & 31;
    if (n >= N_NODES) return;
    const int beg = g_off[n], end = g_off[n + 1];
    const float sdn = g_s2d[n];

    float m = -1e30f;
    for (int i = beg + lane; i < end; i += 32) {
        int s = g_csr_src[i];
        m = fmaxf(m, lrelu(g_s2s[s] + sdn));
    }
#pragma unroll
    for (int off = 16; off > 0; off >>= 1)
        m = fmaxf(m, __shfl_xor_sync(0xffffffffu, m, off));

    float den = 0.f;
    for (int i = beg + lane; i < end; i += 32) {
        int s = g_csr_src[i];
        den += __expf(lrelu(g_s2s[s] + sdn) - m);
    }
#pragma unroll
    for (int off = 16; off > 0; off >>= 1)
        den += __shfl_xor_sync(0xffffffffu, den, off);
    den = fmaxf(den, 1e-16f);

    float acc0 = 0.f, acc1 = 0.f;
    for (int i = beg; i < end; i++) {
        int s = g_csr_src[i];
        float e = lrelu(g_s2s[s] + sdn);
        float alpha = __expf(e - m) / den;
        acc0 += alpha * g_h2[(size_t)s * NCLASS + lane];
        if (lane < 8) acc1 += alpha * g_h2[(size_t)s * NCLASS + 32 + lane];
    }

    float v0 = acc0 + b2[lane];
    float v1 = (lane < 8) ? (acc1 + b2[32 + lane]) : -1e30f;

    float mx = fmaxf(v0, v1);
#pragma unroll
    for (int off = 16; off > 0; off >>= 1)
        mx = fmaxf(mx, __shfl_xor_sync(0xffffffffu, mx, off));
    float se = __expf(v0 - mx) + ((lane < 8) ? __expf(v1 - mx) : 0.f);
#pragma unroll
    for (int off = 16; off > 0; off >>= 1)
        se += __shfl_xor_sync(0xffffffffu, se, off);
    float ls = logf(se);

    out[(size_t)n * NCLASS + lane] = v0 - mx - ls;
    if (lane < 8) out[(size_t)n * NCLASS + 32 + lane] = v1 - mx - ls;
}

// ---------------- launch -----------------------------------------------------
extern "C" void kernel_launch(void* const* d_in, const int* in_sizes, int n_in,
                              void* d_out, int out_size) {
    const float* x  = (const float*)d_in[0];
    const int*   el = (const int*)d_in[1];
    const float* W1 = (const float*)d_in[2];
    const float* a1 = (const float*)d_in[3];
    const float* b1 = (const float*)d_in[4];
    const float* W2 = (const float*)d_in[5];
    const float* a2 = (const float*)d_in[6];
    const float* b2 = (const float*)d_in[7];
    float* out = (float*)d_out;

    const int* src = el;
    const int* dst = el + N_EDGES;

    static cudaStream_t s2 = nullptr;
    static cudaEvent_t ev_fork = nullptr, ev_w = nullptr, ev_join = nullptr;
    if (!s2) {
        cudaStreamCreateWithFlags(&s2, cudaStreamNonBlocking);
        cudaEventCreateWithFlags(&ev_fork, cudaEventDisableTiming);
        cudaEventCreateWithFlags(&ev_w, cudaEventDisableTiming);
        cudaEventCreateWithFlags(&ev_join, cudaEventDisableTiming);
        cudaFuncSetAttribute(k_gemm1_mma, cudaFuncAttributeMaxDynamicSharedMemorySize, G1_SMEM);
        cudaFuncSetAttribute(k_gemm2_mma, cudaFuncAttributeMaxDynamicSharedMemorySize, G2_SMEM);
    }

    const int TB = 256;
    const int NBLK = (N_NODES + 1023) / 1024;

    // fork FIRST
    cudaEventRecord(ev_fork, 0);
    cudaStreamWaitEvent(s2, ev_fork, 0);

    // main: split_x(0); side: split_w(1) runs concurrently
    k_split_x<<<(N_NODES * NFEAT / 8 + TB - 1) / TB, TB>>>(x);                    // 0
    k_split_w<<<(F1 * NFEAT + TB - 1) / TB, TB, 0, s2>>>(W1);                     // 1
    cudaEventRecord(ev_w, s2);
    k_zero_scores<<<(N_NODES * NHEAD + TB - 1) / TB, TB>>>();                     // 2
    cudaStreamWaitEvent(0, ev_w, 0);
    k_gemm1_mma<<<dim3(F1 / G1_BN, (N_NODES + G1_BM - 1) / G1_BM), 256, G1_SMEM>>>(a1); // 3

    // side stream: CSR build + W2 split (concurrent with gemm1)
    k_zero_deg<<<(N_NODES + TB - 1) / TB, TB, 0, s2>>>();
    k_count<<<(N_EDGES + TB - 1) / TB, TB, 0, s2>>>(dst);
    k_scan_blk<<<NBLK, 256, 0, s2>>>();
    k_scan_top<<<1, 32, 0, s2>>>();
    k_scan_add<<<(N_NODES + TB - 1) / TB, TB, 0, s2>>>();
    k_fill<<<(N_EDGES + TB - 1) / TB, TB, 0, s2>>>(src, dst);
    k_split_w2<<<(N2PAD * F1 + TB - 1) / TB, TB, 0, s2>>>(W2);
    cudaEventRecord(ev_join, s2);

    // main stream rejoins, then the dependent chain
    cudaStreamWaitEvent(0, ev_join, 0);
    k_agg1<<<(N_NODES + 7) / 8, 256>>>(b1);
    k_gemm2_mma<<<(N_NODES + G2_BM - 1) / G2_BM, 256, G2_SMEM>>>(a2);
    k_agg2<<<(N_NODES + 7) / 8, 256>>>(b2, out);
}

// round 17
// speedup vs baseline: 1.7329x; 1.0601x over previous
#include <cuda_runtime.h>
#include <cuda_bf16.h>
#include <cuda_fp16.h>
#include <cstdint>

#define N_NODES 50000
#define N_EDGES 800000
#define NFEAT   512
#define NHID    64
#define NHEAD   8
#define F1      512      // NHEAD*NHID
#define NCLASS  40
#define N2PAD   64
#define NEG     0.2f

// ---------------- scratch ---------------------------------------------------
__device__ __half g_h1h[(size_t)N_NODES * F1];   // fp16 gather copy of h1
__device__ float g_h2[(size_t)N_NODES * NCLASS];
__device__ float g_s1s[N_NODES * NHEAD];
__device__ float g_s1d[N_NODES * NHEAD];
__device__ float g_s2s[N_NODES];
__device__ float g_s2d[N_NODES];
__device__ int   g_deg[N_NODES];
__device__ int   g_off[N_NODES + 1];
__device__ int   g_cur[N_NODES];
__device__ int   g_csr_src[N_EDGES];
__device__ int   g_bsum[64];
__device__ int   g_bpre[64];
// fp16 operands
__device__ __half g_xh [(size_t)N_NODES * NFEAT];
__device__ __half g_WTh[F1 * NFEAT];             // [n][k], n = h*64+c
__device__ __half g_zh [(size_t)N_NODES * F1];   // layer-2 input (fp16)
__device__ __half g_W2h[N2PAD * F1];             // [n][k], n padded to 64

__device__ __forceinline__ uint32_t smem_u32(const void* p) {
    uint32_t a;
    asm("{ .reg .u64 t; cvta.to.shared.u64 t, %1; cvt.u32.u64 %0, t; }" : "=r"(a) : "l"(p));
    return a;
}

#define LDSM_X4(r0, r1, r2, r3, addr) \
    asm volatile("ldmatrix.sync.aligned.m8n8.x4.shared.b16 {%0,%1,%2,%3}, [%4];" \
                 : "=r"(r0), "=r"(r1), "=r"(r2), "=r"(r3) : "r"(addr))
#define MMA16816H(acc, a, b0, b1) \
    asm volatile("mma.sync.aligned.m16n8k16.row.col.f32.f16.f16.f32 " \
                 "{%0,%1,%2,%3}, {%4,%5,%6,%7}, {%8,%9}, {%0,%1,%2,%3};" \
                 : "+f"((acc)[0]), "+f"((acc)[1]), "+f"((acc)[2]), "+f"((acc)[3]) \
                 : "r"((a)[0]), "r"((a)[1]), "r"((a)[2]), "r"((a)[3]), "r"(b0), "r"(b1))

// ---------------- CSR construction ------------------------------------------
__global__ void k_zero_deg() {
    int i = blockIdx.x * blockDim.x + threadIdx.x;
    if (i < N_NODES) g_deg[i] = 0;
}
__global__ void k_zero_scores() {
    int i = blockIdx.x * blockDim.x + threadIdx.x;
    if (i < N_NODES * NHEAD) {
        g_s1s[i] = 0.f;
        g_s1d[i] = 0.f;
    }
    if (i < N_NODES) {
        g_s2s[i] = 0.f;
        g_s2d[i] = 0.f;
    }
}
__global__ void k_count(const int* __restrict__ dst) {
    int e = blockIdx.x * blockDim.x + threadIdx.x;
    if (e < N_EDGES) atomicAdd(&g_deg[dst[e]], 1);
}
__global__ __launch_bounds__(256) void k_scan_blk() {
    __shared__ int wsum[8];
    const int blk = blockIdx.x, t = threadIdx.x;
    const int base = blk * 1024 + t * 4;
    int v[4], s = 0;
#pragma unroll
    for (int j = 0; j < 4; j++) {
        int i = base + j;
        v[j] = (i < N_NODES) ? g_deg[i] : 0;
        s += v[j];
    }
    const int lane = t & 31, w = t >> 5;
    int ps = s;
#pragma unroll
    for (int o = 1; o < 32; o <<= 1) {
        int y = __shfl_up_sync(0xffffffffu, ps, o);
        if (lane >= o) ps += y;
    }
    if (lane == 31) wsum[w] = ps;
    __syncthreads();
    if (w == 0) {
        int ws = (lane < 8) ? wsum[lane] : 0;
#pragma unroll
        for (int o = 1; o < 8; o <<= 1) {
            int y = __shfl_up_sync(0xffffffffu, ws, o);
            if (lane >= o) ws += y;
        }
        if (lane < 8) wsum[lane] = ws;
    }
    __syncthreads();
    int run = ps - s + (w > 0 ? wsum[w - 1] : 0);
#pragma unroll
    for (int j = 0; j < 4; j++) {
        int i = base + j;
        if (i < N_NODES) g_off[i] = run;
        run += v[j];
    }
    if (t == 255) g_bsum[blk] = wsum[7];
}
__global__ void k_scan_top() {
    const int lane = threadIdx.x;
    const int nblk = (N_NODES + 1023) / 1024;
    int a = (lane < nblk) ? g_bsum[lane] : 0;
    int b = (lane + 32 < nblk) ? g_bsum[lane + 32] : 0;
    int pa = a;
#pragma unroll
    for (int o = 1; o < 32; o <<= 1) {
        int y = __shfl_up_sync(0xffffffffu, pa, o);
        if (lane >= o) pa += y;
    }
    int tot0 = __shfl_sync(0xffffffffu, pa, 31);
    int pb = b;
#pragma unroll
    for (int o = 1; o < 32; o <<= 1) {
        int y = __shfl_up_sync(0xffffffffu, pb, o);
        if (lane >= o) pb += y;
    }
    if (lane < nblk) g_bpre[lane] = pa - a;
    if (lane + 32 < nblk) g_bpre[lane + 32] = tot0 + pb - b;
}
__global__ void k_scan_add() {
    int i = blockIdx.x * blockDim.x + threadIdx.x;
    if (i < N_NODES) {
        int o = g_off[i] + g_bpre[i >> 10];
        g_off[i] = o;
        g_cur[i] = o;
    }
    if (i == 0) g_off[N_NODES] = N_EDGES;
}
__global__ void k_fill(const int* __restrict__ src, const int* __restrict__ dst) {
    int e = blockIdx.x * blockDim.x + threadIdx.x;
    if (e < N_EDGES) {
        int d = dst[e];
        int p = atomicAdd(&g_cur[d], 1);
        g_csr_src[p] = src[e];
    }
}

// ---------------- operand conversion -----------------------------------------
__global__ void k_split_x(const float* __restrict__ x) {
    int i = blockIdx.x * blockDim.x + threadIdx.x;
    const int total = N_NODES * NFEAT / 8;
    if (i >= total) return;
    const float4* p = (const float4*)x + (size_t)i * 2;
    float4 v0 = p[0], v1 = p[1];
    __half h[8];
    h[0] = __float2half(v0.x); h[1] = __float2half(v0.y);
    h[2] = __float2half(v0.z); h[3] = __float2half(v0.w);
    h[4] = __float2half(v1.x); h[5] = __float2half(v1.y);
    h[6] = __float2half(v1.z); h[7] = __float2half(v1.w);
    *(uint4*)(g_xh + (size_t)i * 8) = *(uint4*)h;
}
__global__ void k_split_w(const float* __restrict__ W1) {
    int idx = blockIdx.x * blockDim.x + threadIdx.x;
    if (idx >= F1 * NFEAT) return;
    int n = idx >> 9, k = idx & 511;
    int h = n >> 6, c = n & 63;
    g_WTh[(size_t)n * NFEAT + k] = __float2half(W1[((size_t)h * NFEAT + k) * NHID + c]);
}
__global__ void k_split_w2(const float* __restrict__ W2) {
    int idx = blockIdx.x * blockDim.x + threadIdx.x;
    if (idx >= N2PAD * F1) return;
    int n = idx >> 9, k = idx & 511;
    float w = (n < NCLASS) ? W2[(size_t)k * NCLASS + n] : 0.f;
    g_W2h[(size_t)n * F1 + k] = __float2half(w);
}

// ---------------- GEMM1 (pure fp16 HMMA, BK=64, + fused scores) --------------
#define G1_BM     128
#define G1_BN     128
#define G1_BK     64
#define G1_KITER  8                  // 512 / 64
#define G1_ROWB   144                // 64 halves (128B) + 16B pad
#define G1_REG    (128 * G1_ROWB)    // 18432
#define G1_STAGE  (2 * G1_REG)       // A | B = 36864
#define G1_NSTG   2
#define G1_SMEM   (G1_NSTG * G1_STAGE)   // 73728

__device__ __forceinline__ void g1_prefetch(int kb, uint32_t stage, int bm, int bn, int t) {
    const int k_in = kb * G1_BK;
#pragma unroll
    for (int i = 0; i < 8; i++) {
        int q = t + i * 256;
        int region = q >> 10;         // 0:A 1:B
        int idx = q & 1023;
        int row = idx >> 3, c = idx & 7;
        uint32_t dst = stage + region * G1_REG + row * G1_ROWB + c * 16;
        if (region == 0) {
            int grow = bm + row;
            int ok = grow < N_NODES;
            if (!ok) grow = 0;
            const void* srcp = g_xh + (size_t)grow * NFEAT + k_in + c * 8;
            int sz = ok ? 16 : 0;
            asm volatile("cp.async.cg.shared.global [%0], [%1], 16, %2;"
                         :: "r"(dst), "l"(srcp), "r"(sz));
        } else {
            const void* srcp = g_WTh + (size_t)(bn + row) * NFEAT + k_in + c * 8;
            asm volatile("cp.async.cg.shared.global [%0], [%1], 16;"
                         :: "r"(dst), "l"(srcp));
        }
    }
}

__global__ __launch_bounds__(256, 2) void k_gemm1_mma(const float* __restrict__ a1) {
    extern __shared__ char dyn[];
    const uint32_t sbase = smem_u32(dyn);
    const int t    = threadIdx.x;
    const int wid  = t >> 5;
    const int lane = t & 31;
    const int bm   = blockIdx.y * G1_BM;
    const int bn   = blockIdx.x * G1_BN;
    const int mw   = (wid >> 2) * 64;
    const int nw   = (wid & 3) * 32;

    float acc[4][4][4];
#pragma unroll
    for (int mt = 0; mt < 4; mt++)
#pragma unroll
        for (int nt = 0; nt < 4; nt++)
#pragma unroll
            for (int j = 0; j < 4; j++) acc[mt][nt][j] = 0.f;

    g1_prefetch(0, sbase, bm, bn, t);
    asm volatile("cp.async.commit_group;");
    g1_prefetch(1, sbase + G1_STAGE, bm, bn, t);
    asm volatile("cp.async.commit_group;");

    const uint32_t a_off = (mw + (lane & 15)) * G1_ROWB + ((lane >> 4) * 16);
    const uint32_t b_off = G1_REG + (nw + (lane & 7) + ((lane >> 4) << 3)) * G1_ROWB + (((lane >> 3) & 1) * 16);

    for (int kb = 0; kb < G1_KITER; kb++) {
        asm volatile("cp.async.wait_group 1;");
        __syncthreads();
        const uint32_t stage = sbase + (kb & 1) * G1_STAGE;

#pragma unroll
        for (int ks = 0; ks < 4; ks++) {
            uint32_t a[4][4];
#pragma unroll
            for (int mt = 0; mt < 4; mt++) {
                uint32_t ad = stage + a_off + mt * (16 * G1_ROWB) + ks * 32;
                LDSM_X4(a[mt][0], a[mt][1], a[mt][2], a[mt][3], ad);
            }
            uint32_t b[2][4];
#pragma unroll
            for (int np = 0; np < 2; np++) {
                uint32_t bd = stage + b_off + np * (16 * G1_ROWB) + ks * 32;
                LDSM_X4(b[np][0], b[np][1], b[np][2], b[np][3], bd);
            }
#pragma unroll
            for (int mt = 0; mt < 4; mt++)
#pragma unroll
                for (int nt = 0; nt < 4; nt++) {
                    const uint32_t b0 = b[nt >> 1][(nt & 1) * 2];
                    const uint32_t b1 = b[nt >> 1][(nt & 1) * 2 + 1];
                    MMA16816H(acc[mt][nt], a[mt], b0, b1);
                }
        }
        __syncthreads();
        if (kb + G1_NSTG < G1_KITER)
            g1_prefetch(kb + G1_NSTG, stage, bm, bn, t);
        asm volatile("cp.async.commit_group;");
    }

    // epilogue: fp16 h1h + fused layer-1 attention scores
    const int r_base = bm + mw + (lane >> 2);
    const int hw = (bn + nw) >> 6;
    const int co0 = ((bn + nw) & 63) + (lane & 3) * 2;
#pragma unroll
    for (int mt = 0; mt < 4; mt++) {
#pragma unroll
        for (int nt = 0; nt < 4; nt++) {
            int r0 = r_base + mt * 16;
            int cc = bn + nw + (lane & 3) * 2 + nt * 8;
            if (r0 < N_NODES)
                *(__half2*)(g_h1h + (size_t)r0 * F1 + cc) = __floats2half2_rn(acc[mt][nt][0], acc[mt][nt][1]);
            if (r0 + 8 < N_NODES)
                *(__half2*)(g_h1h + (size_t)(r0 + 8) * F1 + cc) = __floats2half2_rn(acc[mt][nt][2], acc[mt][nt][3]);
        }
        float s0 = 0.f, d0 = 0.f, s1 = 0.f, d1 = 0.f;
#pragma unroll
        for (int nt = 0; nt < 4; nt++) {
#pragma unroll
            for (int je = 0; je < 2; je++) {
                int co = co0 + nt * 8 + je;
                float a_s = a1[hw * 128 + co];
                float a_d = a1[hw * 128 + 64 + co];
                s0 += acc[mt][nt][je] * a_s;
                d0 += acc[mt][nt][je] * a_d;
                s1 += acc[mt][nt][2 + je] * a_s;
                d1 += acc[mt][nt][2 + je] * a_d;
            }
        }
        s0 += __shfl_xor_sync(0xffffffffu, s0, 1); s0 += __shfl_xor_sync(0xffffffffu, s0, 2);
        d0 += __shfl_xor_sync(0xffffffffu, d0, 1); d0 += __shfl_xor_sync(0xffffffffu, d0, 2);
        s1 += __shfl_xor_sync(0xffffffffu, s1, 1); s1 += __shfl_xor_sync(0xffffffffu, s1, 2);
        d1 += __shfl_xor_sync(0xffffffffu, d1, 1); d1 += __shfl_xor_sync(0xffffffffu, d1, 2);
        if ((lane & 3) == 0) {
            int r0 = r_base + mt * 16;
            if (r0 < N_NODES) {
                atomicAdd(&g_s1s[r0 * NHEAD + hw], s0);
                atomicAdd(&g_s1d[r0 * NHEAD + hw], d0);
            }
            if (r0 + 8 < N_NODES) {
                atomicAdd(&g_s1s[(r0 + 8) * NHEAD + hw], s1);
                atomicAdd(&g_s1d[(r0 + 8) * NHEAD + hw], d1);
            }
        }
    }
}

// ---------------- GEMM2 (pure fp16 HMMA + fused layer-2 scores) --------------
#define G2_BM     128
#define G2_KITER  16
#define G2_ROWB   80
#define G2_AREG   10240
#define G2_BREG   5120
#define G2_STAGE  (G2_AREG + G2_BREG)    // 15360
#define G2_NSTG   3
#define G2_SMEM   (G2_NSTG * G2_STAGE)   // 46080

__device__ __forceinline__ void g2_prefetch(int kb, uint32_t stage, int bm, int t) {
    const int k_in = kb * 32;
#pragma unroll
    for (int i = 0; i < 3; i++) {
        int q = t + i * 256;
        if (q < 512) {                  // A: 128 rows x 4 chunks
            int row = q >> 2, c = q & 3;
            uint32_t dst = stage + row * G2_ROWB + c * 16;
            int grow = bm + row;
            int ok = grow < N_NODES;
            if (!ok) grow = 0;
            const void* srcp = g_zh + (size_t)grow * F1 + k_in + c * 8;
            int sz = ok ? 16 : 0;
            asm volatile("cp.async.cg.shared.global [%0], [%1], 16, %2;"
                         :: "r"(dst), "l"(srcp), "r"(sz));
        } else {                        // B: 64 rows x 4 chunks
            int qb = q - 512;
            int row = qb >> 2, c = qb & 3;
            uint32_t dst = stage + G2_AREG + row * G2_ROWB + c * 16;
            const void* srcp = g_W2h + (size_t)row * F1 + k_in + c * 8;
            asm volatile("cp.async.cg.shared.global [%0], [%1], 16;"
                         :: "r"(dst), "l"(srcp));
        }
    }
}

__global__ __launch_bounds__(256, 2) void k_gemm2_mma(const float* __restrict__ a2) {
    extern __shared__ char dyn[];
    const uint32_t sbase = smem_u32(dyn);
    const int t    = threadIdx.x;
    const int wid  = t >> 5;
    const int lane = t & 31;
    const int bm   = blockIdx.x * G2_BM;
    const int mw   = (wid >> 1) * 32;
    const int nw   = (wid & 1) * 32;

    float acc[2][4][4];
#pragma unroll
    for (int mt = 0; mt < 2; mt++)
#pragma unroll
        for (int nt = 0; nt < 4; nt++)
#pragma unroll
            for (int j = 0; j < 4; j++) acc[mt][nt][j] = 0.f;

    g2_prefetch(0, sbase, bm, t);
    asm volatile("cp.async.commit_group;");
    g2_prefetch(1, sbase + G2_STAGE, bm, t);
    asm volatile("cp.async.commit_group;");
    g2_prefetch(2, sbase + 2 * G2_STAGE, bm, t);
    asm volatile("cp.async.commit_group;");

    const uint32_t a_off = (mw + (lane & 15)) * G2_ROWB + ((lane >> 4) * 16);
    const uint32_t b_off = G2_AREG + (nw + (lane & 7) + ((lane >> 4) << 3)) * G2_ROWB + (((lane >> 3) & 1) * 16);

    int st = 0;
    for (int kb = 0; kb < G2_KITER; kb++) {
        asm volatile("cp.async.wait_group 2;");
        __syncthreads();
        const uint32_t stage = sbase + st * G2_STAGE;

#pragma unroll
        for (int ks = 0; ks < 2; ks++) {
            uint32_t a[2][4];
#pragma unroll
            for (int mt = 0; mt < 2; mt++) {
                uint32_t ad = stage + a_off + mt * (16 * G2_ROWB) + ks * 32;
                LDSM_X4(a[mt][0], a[mt][1], a[mt][2], a[mt][3], ad);
            }
            uint32_t b[2][4];
#pragma unroll
            for (int np = 0; np < 2; np++) {
                uint32_t bd = stage + b_off + np * (16 * G2_ROWB) + ks * 32;
                LDSM_X4(b[np][0], b[np][1], b[np][2], b[np][3], bd);
            }
#pragma unroll
            for (int mt = 0; mt < 2; mt++)
#pragma unroll
                for (int nt = 0; nt < 4; nt++) {
                    const uint32_t b0 = b[nt >> 1][(nt & 1) * 2];
                    const uint32_t b1 = b[nt >> 1][(nt & 1) * 2 + 1];
                    MMA16816H(acc[mt][nt], a[mt], b0, b1);
                }
        }
        __syncthreads();
        if (kb + G2_NSTG < G2_KITER)
            g2_prefetch(kb + G2_NSTG, stage, bm, t);
        asm volatile("cp.async.commit_group;");
        st = (st == G2_NSTG - 1) ? 0 : st + 1;
    }

    // epilogue: h2 store + fused layer-2 scores
    const int r_base = bm + mw + (lane >> 2);
    const int c_base = nw + (lane & 3) * 2;
#pragma unroll
    for (int mt = 0; mt < 2; mt++) {
#pragma unroll
        for (int nt = 0; nt < 4; nt++) {
            int r0 = r_base + mt * 16;
            int cc = c_base + nt * 8;
            if (cc < NCLASS) {
                if (r0 < N_NODES)
                    *(float2*)(g_h2 + (size_t)r0 * NCLASS + cc) = make_float2(acc[mt][nt][0], acc[mt][nt][1]);
                if (r0 + 8 < N_NODES)
                    *(float2*)(g_h2 + (size_t)(r0 + 8) * NCLASS + cc) = make_float2(acc[mt][nt][2], acc[mt][nt][3]);
            }
        }
    }
#pragma unroll
    for (int mt = 0; mt < 2; mt++) {
        float s0 = 0.f, d0 = 0.f, s1 = 0.f, d1 = 0.f;
#pragma unroll
        for (int nt = 0; nt < 4; nt++) {
#pragma unroll
            for (int je = 0; je < 2; je++) {
                int cc = c_base + nt * 8 + je;
                float a_s = (cc < NCLASS) ? a2[cc] : 0.f;
                float a_d = (cc < NCLASS) ? a2[NCLASS + cc] : 0.f;
                s0 += acc[mt][nt][je] * a_s;
                d0 += acc[mt][nt][je] * a_d;
                s1 += acc[mt][nt][2 + je] * a_s;
                d1 += acc[mt][nt][2 + je] * a_d;
            }
        }
        s0 += __shfl_xor_sync(0xffffffffu, s0, 1); s0 += __shfl_xor_sync(0xffffffffu, s0, 2);
        d0 += __shfl_xor_sync(0xffffffffu, d0, 1); d0 += __shfl_xor_sync(0xffffffffu, d0, 2);
        s1 += __shfl_xor_sync(0xffffffffu, s1, 1); s1 += __shfl_xor_sync(0xffffffffu, s1, 2);
        d1 += __shfl_xor_sync(0xffffffffu, d1, 1); d1 += __shfl_xor_sync(0xffffffffu, d1, 2);
        if ((lane & 3) == 0) {
            int r0 = r_base + mt * 16;
            if (r0 < N_NODES) {
                atomicAdd(&g_s2s[r0], s0);
                atomicAdd(&g_s2d[r0], d0);
            }
            if (r0 + 8 < N_NODES) {
                atomicAdd(&g_s2s[r0 + 8], s1);
                atomicAdd(&g_s2d[r0 + 8], d1);
            }
        }
    }
}

__device__ __forceinline__ float lrelu(float x) { return x > 0.f ? x : NEG * x; }

// ---------------- layer-1 softmax-aggregate (4-edge unrolled gather) --------
__device__ __forceinline__ void agg_edge(int s, float alpha, float* acc, int lane) {
    const uint4* hp = (const uint4*)(g_h1h + (size_t)s * F1 + lane * 16);
    uint4 q0 = hp[0];
    uint4 q1 = hp[1];
    float2 f;
    f = __half22float2(*(__half2*)&q0.x); acc[0] += alpha * f.x; acc[1] += alpha * f.y;
    f = __half22float2(*(__half2*)&q0.y); acc[2] += alpha * f.x; acc[3] += alpha * f.y;
    f = __half22float2(*(__half2*)&q0.z); acc[4] += alpha * f.x; acc[5] += alpha * f.y;
    f = __half22float2(*(__half2*)&q0.w); acc[6] += alpha * f.x; acc[7] += alpha * f.y;
    f = __half22float2(*(__half2*)&q1.x); acc[8] += alpha * f.x; acc[9] += alpha * f.y;
    f = __half22float2(*(__half2*)&q1.y); acc[10] += alpha * f.x; acc[11] += alpha * f.y;
    f = __half22float2(*(__half2*)&q1.z); acc[12] += alpha * f.x; acc[13] += alpha * f.y;
    f = __half22float2(*(__half2*)&q1.w); acc[14] += alpha * f.x; acc[15] += alpha * f.y;
}

__global__ __launch_bounds__(256) void k_agg1(const float* __restrict__ b1) {
    int n    = (blockIdx.x * blockDim.x + threadIdx.x) >> 5;
    int lane = threadIdx.x & 31;
    if (n >= N_NODES) return;
    const int beg = g_off[n], end = g_off[n + 1];

    const int h  = lane & 7;
    const int es = lane >> 3;
    const float sdh = g_s1d[n * NHEAD + h];

    float m = -1e30f;
    for (int i = beg + es; i < end; i += 4) {
        int s = g_csr_src[i];
        float e = lrelu(g_s1s[s * NHEAD + h] + sdh);
        m = fmaxf(m, e);
    }
    m = fmaxf(m, __shfl_xor_sync(0xffffffffu, m, 8));
    m = fmaxf(m, __shfl_xor_sync(0xffffffffu, m, 16));

    float den = 0.f;
    for (int i = beg + es; i < end; i += 4) {
        int s = g_csr_src[i];
        float e = lrelu(g_s1s[s * NHEAD + h] + sdh);
        den += __expf(e - m);
    }
    den += __shfl_xor_sync(0xffffffffu, den, 8);
    den += __shfl_xor_sync(0xffffffffu, den, 16);
    den = fmaxf(den, 1e-16f);
    const float rden = 1.f / den;

    float acc[16];
#pragma unroll
    for (int j = 0; j < 16; j++) acc[j] = 0.f;
    const int hl = lane >> 2;

    int i = beg;
    for (; i + 3 < end; i += 4) {
        int s0 = g_csr_src[i];
        int s1 = g_csr_src[i + 1];
        int s2 = g_csr_src[i + 2];
        int s3 = g_csr_src[i + 3];
        float al0 = 0.f, al1 = 0.f, al2 = 0.f, al3 = 0.f;
        if (lane < 8) {
            al0 = __expf(lrelu(g_s1s[s0 * NHEAD + lane] + sdh) - m) * rden;
            al1 = __expf(lrelu(g_s1s[s1 * NHEAD + lane] + sdh) - m) * rden;
            al2 = __expf(lrelu(g_s1s[s2 * NHEAD + lane] + sdh) - m) * rden;
            al3 = __expf(lrelu(g_s1s[s3 * NHEAD + lane] + sdh) - m) * rden;
        }
        al0 = __shfl_sync(0xffffffffu, al0, hl);
        al1 = __shfl_sync(0xffffffffu, al1, hl);
        al2 = __shfl_sync(0xffffffffu, al2, hl);
        al3 = __shfl_sync(0xffffffffu, al3, hl);
        agg_edge(s0, al0, acc, lane);
        agg_edge(s1, al1, acc, lane);
        agg_edge(s2, al2, acc, lane);
        agg_edge(s3, al3, acc, lane);
    }
    for (; i < end; i++) {
        int s0 = g_csr_src[i];
        float al0 = 0.f;
        if (lane < 8)
            al0 = __expf(lrelu(g_s1s[s0 * NHEAD + lane] + sdh) - m) * rden;
        al0 = __shfl_sync(0xffffffffu, al0, hl);
        agg_edge(s0, al0, acc, lane);
    }

    const float4* bp = (const float4*)(b1 + lane * 16);
    __half zh[16];
#pragma unroll
    for (int j = 0; j < 4; j++) {
        float4 b = bp[j];
        float v[4];
        v[0] = acc[j * 4 + 0] + b.x;
        v[1] = acc[j * 4 + 1] + b.y;
        v[2] = acc[j * 4 + 2] + b.z;
        v[3] = acc[j * 4 + 3] + b.w;
#pragma unroll
        for (int q = 0; q < 4; q++) {
            float e = v[q] > 0.f ? v[q] : expm1f(v[q]);
            zh[j * 4 + q] = __float2half(e);
        }
    }
    *(uint4*)(g_zh + (size_t)n * F1 + lane * 16)     = *(uint4*)(zh);
    *(uint4*)(g_zh + (size_t)n * F1 + lane * 16 + 8) = *(uint4*)(zh + 8);
}

// ---------------- layer-2 aggregate + bias + log_softmax --------------------
__global__ __launch_bounds__(256) void k_agg2(const float* __restrict__ b2,
                                              float* __restrict__ out) {
    int n    = (blockIdx.x * blockDim.x + threadIdx.x) >> 5;
    int lane = threadIdx.x & 31;
    if (n >= N_NODES) return;
    const int beg = g_off[n], end = g_off[n + 1];
    const float sdn = g_s2d[n];

    float m = -1e30f;
    for (int i = beg + lane; i < end; i += 32) {
        int s = g_csr_src[i];
        m = fmaxf(m, lrelu(g_s2s[s] + sdn));
    }
#pragma unroll
    for (int off = 16; off > 0; off >>= 1)
        m = fmaxf(m, __shfl_xor_sync(0xffffffffu, m, off));

    float den = 0.f;
    for (int i = beg + lane; i < end; i += 32) {
        int s = g_csr_src[i];
        den += __expf(lrelu(g_s2s[s] + sdn) - m);
    }
#pragma unroll
    for (int off = 16; off > 0; off >>= 1)
        den += __shfl_xor_sync(0xffffffffu, den, off);
    den = fmaxf(den, 1e-16f);

    float acc0 = 0.f, acc1 = 0.f;
    for (int i = beg; i < end; i++) {
        int s = g_csr_src[i];
        float e = lrelu(g_s2s[s] + sdn);
        float alpha = __expf(e - m) / den;
        acc0 += alpha * g_h2[(size_t)s * NCLASS + lane];
        if (lane < 8) acc1 += alpha * g_h2[(size_t)s * NCLASS + 32 + lane];
    }

    float v0 = acc0 + b2[lane];
    float v1 = (lane < 8) ? (acc1 + b2[32 + lane]) : -1e30f;

    float mx = fmaxf(v0, v1);
#pragma unroll
    for (int off = 16; off > 0; off >>= 1)
        mx = fmaxf(mx, __shfl_xor_sync(0xffffffffu, mx, off));
    float se = __expf(v0 - mx) + ((lane < 8) ? __expf(v1 - mx) : 0.f);
#pragma unroll
    for (int off = 16; off > 0; off >>= 1)
        se += __shfl_xor_sync(0xffffffffu, se, off);
    float ls = logf(se);

    out[(size_t)n * NCLASS + lane] = v0 - mx - ls;
    if (lane < 8) out[(size_t)n * NCLASS + 32 + lane] = v1 - mx - ls;
}

// ---------------- launch -----------------------------------------------------
extern "C" void kernel_launch(void* const* d_in, const int* in_sizes, int n_in,
                              void* d_out, int out_size) {
    const float* x  = (const float*)d_in[0];
    const int*   el = (const int*)d_in[1];
    const float* W1 = (const float*)d_in[2];
    const float* a1 = (const float*)d_in[3];
    const float* b1 = (const float*)d_in[4];
    const float* W2 = (const float*)d_in[5];
    const float* a2 = (const float*)d_in[6];
    const float* b2 = (const float*)d_in[7];
    float* out = (float*)d_out;

    const int* src = el;
    const int* dst = el + N_EDGES;

    static cudaStream_t s2 = nullptr;
    static cudaEvent_t ev_fork = nullptr, ev_w = nullptr, ev_join = nullptr;
    if (!s2) {
        cudaStreamCreateWithFlags(&s2, cudaStreamNonBlocking);
        cudaEventCreateWithFlags(&ev_fork, cudaEventDisableTiming);
        cudaEventCreateWithFlags(&ev_w, cudaEventDisableTiming);
        cudaEventCreateWithFlags(&ev_join, cudaEventDisableTiming);
        cudaFuncSetAttribute(k_gemm1_mma, cudaFuncAttributeMaxDynamicSharedMemorySize, G1_SMEM);
        cudaFuncSetAttribute(k_gemm2_mma, cudaFuncAttributeMaxDynamicSharedMemorySize, G2_SMEM);
    }

    const int TB = 256;
    const int NBLK = (N_NODES + 1023) / 1024;

    // fork FIRST
    cudaEventRecord(ev_fork, 0);
    cudaStreamWaitEvent(s2, ev_fork, 0);

    // main: split_x(0); side: split_w(1) runs concurrently
    k_split_x<<<(N_NODES * NFEAT / 8 + TB - 1) / TB, TB>>>(x);                    // 0
    k_split_w<<<(F1 * NFEAT + TB - 1) / TB, TB, 0, s2>>>(W1);                     // 1
    cudaEventRecord(ev_w, s2);
    k_zero_scores<<<(N_NODES * NHEAD + TB - 1) / TB, TB>>>();                     // 2
    cudaStreamWaitEvent(0, ev_w, 0);
    k_gemm1_mma<<<dim3(F1 / G1_BN, (N_NODES + G1_BM - 1) / G1_BM), 256, G1_SMEM>>>(a1); // 3

    // side stream: CSR build + W2 split (concurrent with gemm1)
    k_zero_deg<<<(N_NODES + TB - 1) / TB, TB, 0, s2>>>();
    k_count<<<(N_EDGES + TB - 1) / TB, TB, 0, s2>>>(dst);
    k_scan_blk<<<NBLK, 256, 0, s2>>>();
    k_scan_top<<<1, 32, 0, s2>>>();
    k_scan_add<<<(N_NODES + TB - 1) / TB, TB, 0, s2>>>();
    k_fill<<<(N_EDGES + TB - 1) / TB, TB, 0, s2>>>(src, dst);
    k_split_w2<<<(N2PAD * F1 + TB - 1) / TB, TB, 0, s2>>>(W2);
    cudaEventRecord(ev_join, s2);

    // main stream rejoins, then the dependent chain
    cudaStreamWaitEvent(0, ev_join, 0);
    k_agg1<<<(N_NODES + 7) / 8, 256>>>(b1);
    k_gemm2_mma<<<(N_NODES + G2_BM - 1) / G2_BM, 256, G2_SMEM>>>(a2);
    k_agg2<<<(N_NODES + 7) / 8, 256>>>(b2, out);
}